// round 4
// baseline (speedup 1.0000x reference)
#include <cuda_runtime.h>
#include <cstdint>

#define BB 4
#define DD 512
#define NN 1536
#define HH 8
#define DH 64          // per-head dim

// ---------------- scratch (device globals; no allocation allowed) ----------
__device__ float g_q[(size_t)BB * HH * DH * NN];   // [b,h,d,n]
__device__ float g_k[(size_t)BB * HH * DH * NN];   // [b,h,d,n]
__device__ float g_v[(size_t)BB * HH * DH * NN];   // [b,h,d,n]  (same layout as Q/K)
__device__ float g_s[(size_t)BB * HH * NN * NN];   // scores -> probs, [b,h,n,m]
__device__ float g_x[(size_t)BB * DD * NN];        // [b,c,n]
__device__ unsigned char g_mask[(size_t)NN * NN];  // canonical 0/1 mask
__device__ unsigned g_minenc;
__device__ unsigned g_maskflags;

// order-preserving float <-> uint encoding
__device__ __forceinline__ unsigned enc_f(float x) {
    unsigned b = __float_as_uint(x);
    return (b & 0x80000000u) ? ~b : (b | 0x80000000u);
}
__device__ __forceinline__ float dec_f(unsigned e) {
    return (e & 0x80000000u) ? __uint_as_float(e ^ 0x80000000u)
                             : __uint_as_float(~e);
}

__global__ void init_kernel() { g_minenc = 0xFFFFFFFFu; g_maskflags = 0u; }

// ---------------- mask dtype classification + normalization ----------------
__global__ void __launch_bounds__(256)
mask_classify_kernel(const unsigned* __restrict__ mw) {
    const int total = NN * NN / 4;
    unsigned local = 0;
    for (int i = blockIdx.x * 256 + threadIdx.x; i < total; i += gridDim.x * 256) {
        unsigned w = mw[i];
        if (w != 0u && w != 1u)          local |= 1u;
        if (w != 0u && w != 0x3f800000u) local |= 2u;
    }
#pragma unroll
    for (int o = 16; o > 0; o >>= 1) local |= __shfl_xor_sync(0xffffffffu, local, o);
    if ((threadIdx.x & 31) == 0 && local) atomicOr(&g_maskflags, local);
}

__global__ void __launch_bounds__(256)
mask_convert_kernel(const void* __restrict__ mraw) {
    const unsigned f = g_maskflags;
    const int mode = ((f & 2u) == 0u) ? 2 : (((f & 1u) == 0u) ? 1 : 0);
    const int total = NN * NN;
    if (mode == 0) {
        const unsigned char* m8 = (const unsigned char*)mraw;
        for (int i = blockIdx.x * 256 + threadIdx.x; i < total; i += gridDim.x * 256)
            g_mask[i] = m8[i] ? 1 : 0;
    } else if (mode == 1) {
        const int* mi = (const int*)mraw;
        for (int i = blockIdx.x * 256 + threadIdx.x; i < total; i += gridDim.x * 256)
            g_mask[i] = mi[i] ? 1 : 0;
    } else {
        const float* mf = (const float*)mraw;
        for (int i = blockIdx.x * 256 + threadIdx.x; i < total; i += gridDim.x * 256)
            g_mask[i] = (mf[i] != 0.0f) ? 1 : 0;
    }
}

// ---------------- projection: Y[b,o,n] = sum_c W[o,c] X[b,c,n] + bias[o] ----
// 64(o) x 128(n) tile, 128 threads, 8x8 per thread, k-step 16, double buffered
// MODE 0: plain [b,o,n]; MODE 1: head [b,h,d,n]
template <int MODE>
__global__ void __launch_bounds__(128)
proj_kernel(const float* __restrict__ X, const float* __restrict__ W,
            const float* __restrict__ bias, float* __restrict__ Y) {
    __shared__ float sA[2][16][64];   // [buf][c][o]
    __shared__ float sB[2][16][128];  // [buf][c][n]
    const int b  = blockIdx.z;
    const int o0 = blockIdx.y * 64;
    const int n0 = blockIdx.x * 128;
    const int t  = threadIdx.x;
    const int tx = t & 15, ty = t >> 4;           // tx: n group, ty: o group
    const float* Xb = X + (size_t)b * DD * NN;

    const int aro = t >> 1, ac0 = (t & 1) * 8;    // A load: o row, c offset
    const int brc = t >> 3, bn0 = (t & 7) * 16;   // B load: c row, n offset

    float4 pa0, pa1, pb0, pb1, pb2, pb3;
    const float* wrow = &W[(size_t)(o0 + aro) * DD];
    pa0 = *(const float4*)&wrow[ac0];
    pa1 = *(const float4*)&wrow[ac0 + 4];
    pb0 = *(const float4*)&Xb[(size_t)brc * NN + n0 + bn0];
    pb1 = *(const float4*)&Xb[(size_t)brc * NN + n0 + bn0 + 4];
    pb2 = *(const float4*)&Xb[(size_t)brc * NN + n0 + bn0 + 8];
    pb3 = *(const float4*)&Xb[(size_t)brc * NN + n0 + bn0 + 12];
    sA[0][ac0 + 0][aro] = pa0.x; sA[0][ac0 + 1][aro] = pa0.y;
    sA[0][ac0 + 2][aro] = pa0.z; sA[0][ac0 + 3][aro] = pa0.w;
    sA[0][ac0 + 4][aro] = pa1.x; sA[0][ac0 + 5][aro] = pa1.y;
    sA[0][ac0 + 6][aro] = pa1.z; sA[0][ac0 + 7][aro] = pa1.w;
    *(float4*)&sB[0][brc][bn0 + 0]  = pb0;
    *(float4*)&sB[0][brc][bn0 + 4]  = pb1;
    *(float4*)&sB[0][brc][bn0 + 8]  = pb2;
    *(float4*)&sB[0][brc][bn0 + 12] = pb3;
    __syncthreads();

    float acc[8][8] = {};
    const int NK = DD / 16;
    for (int kt = 0; kt < NK; kt++) {
        const int cur = kt & 1;
        if (kt + 1 < NK) {
            const int c0 = (kt + 1) * 16;
            pa0 = *(const float4*)&wrow[c0 + ac0];
            pa1 = *(const float4*)&wrow[c0 + ac0 + 4];
            pb0 = *(const float4*)&Xb[(size_t)(c0 + brc) * NN + n0 + bn0];
            pb1 = *(const float4*)&Xb[(size_t)(c0 + brc) * NN + n0 + bn0 + 4];
            pb2 = *(const float4*)&Xb[(size_t)(c0 + brc) * NN + n0 + bn0 + 8];
            pb3 = *(const float4*)&Xb[(size_t)(c0 + brc) * NN + n0 + bn0 + 12];
        }
#pragma unroll
        for (int k = 0; k < 16; k++) {
            float a[8], bb[8];
            *(float4*)&a[0]  = *(const float4*)&sA[cur][k][ty * 8];
            *(float4*)&a[4]  = *(const float4*)&sA[cur][k][ty * 8 + 4];
            *(float4*)&bb[0] = *(const float4*)&sB[cur][k][tx * 8];
            *(float4*)&bb[4] = *(const float4*)&sB[cur][k][tx * 8 + 4];
#pragma unroll
            for (int i = 0; i < 8; i++)
#pragma unroll
                for (int j = 0; j < 8; j++) acc[i][j] += a[i] * bb[j];
        }
        if (kt + 1 < NK) {
            const int nx = cur ^ 1;
            sA[nx][ac0 + 0][aro] = pa0.x; sA[nx][ac0 + 1][aro] = pa0.y;
            sA[nx][ac0 + 2][aro] = pa0.z; sA[nx][ac0 + 3][aro] = pa0.w;
            sA[nx][ac0 + 4][aro] = pa1.x; sA[nx][ac0 + 5][aro] = pa1.y;
            sA[nx][ac0 + 6][aro] = pa1.z; sA[nx][ac0 + 7][aro] = pa1.w;
            *(float4*)&sB[nx][brc][bn0 + 0]  = pb0;
            *(float4*)&sB[nx][brc][bn0 + 4]  = pb1;
            *(float4*)&sB[nx][brc][bn0 + 8]  = pb2;
            *(float4*)&sB[nx][brc][bn0 + 12] = pb3;
        }
        __syncthreads();
    }

#pragma unroll
    for (int i = 0; i < 8; i++) {
        const int o = o0 + ty * 8 + i;
        const float bo = bias[o];
        float4 r0 = make_float4(acc[i][0] + bo, acc[i][1] + bo, acc[i][2] + bo, acc[i][3] + bo);
        float4 r1 = make_float4(acc[i][4] + bo, acc[i][5] + bo, acc[i][6] + bo, acc[i][7] + bo);
        if (MODE == 0) {
            float* p = &Y[((size_t)b * DD + o) * NN + n0 + tx * 8];
            *(float4*)&p[0] = r0; *(float4*)&p[4] = r1;
        } else {
            const int h = o & 7, dd = o >> 3;
            float* p = &Y[(((size_t)b * HH + h) * DH + dd) * NN + n0 + tx * 8];
            *(float4*)&p[0] = r0; *(float4*)&p[4] = r1;
        }
    }
}

// ---------------- scores: S[bh,n,m] = (1/8) sum_d Q[bh,d,n] K[bh,d,m] -------
// 128x128 tile, 256 threads, 8x8 per thread, k-step 16 double buffered (K=64)
__global__ void __launch_bounds__(256)
scores_kernel() {
    __shared__ float sQ[2][16][128];  // [buf][d][n]
    __shared__ float sK[2][16][128];  // [buf][d][m]
    __shared__ float sred[8];
    const int bh = blockIdx.z;
    const int n0 = blockIdx.y * 128;
    const int m0 = blockIdx.x * 128;
    const int t  = threadIdx.x;
    const int tx = t & 15, ty = t >> 4;
    const float* Q = g_q + (size_t)bh * DH * NN;
    const float* K = g_k + (size_t)bh * DH * NN;

    const int lr = t >> 4, lc = (t & 15) * 8;  // load: d row (0..15), col offset

    float4 q0, q1, k0, k1;
    q0 = *(const float4*)&Q[(size_t)lr * NN + n0 + lc];
    q1 = *(const float4*)&Q[(size_t)lr * NN + n0 + lc + 4];
    k0 = *(const float4*)&K[(size_t)lr * NN + m0 + lc];
    k1 = *(const float4*)&K[(size_t)lr * NN + m0 + lc + 4];
    *(float4*)&sQ[0][lr][lc]     = q0;
    *(float4*)&sQ[0][lr][lc + 4] = q1;
    *(float4*)&sK[0][lr][lc]     = k0;
    *(float4*)&sK[0][lr][lc + 4] = k1;
    __syncthreads();

    float acc[8][8] = {};
    const int NK = DH / 16;  // 4
    for (int kt = 0; kt < NK; kt++) {
        const int cur = kt & 1;
        if (kt + 1 < NK) {
            const int d0 = (kt + 1) * 16;
            q0 = *(const float4*)&Q[(size_t)(d0 + lr) * NN + n0 + lc];
            q1 = *(const float4*)&Q[(size_t)(d0 + lr) * NN + n0 + lc + 4];
            k0 = *(const float4*)&K[(size_t)(d0 + lr) * NN + m0 + lc];
            k1 = *(const float4*)&K[(size_t)(d0 + lr) * NN + m0 + lc + 4];
        }
#pragma unroll
        for (int k = 0; k < 16; k++) {
            float a[8], bb[8];
            *(float4*)&a[0]  = *(const float4*)&sQ[cur][k][ty * 8];
            *(float4*)&a[4]  = *(const float4*)&sQ[cur][k][ty * 8 + 4];
            *(float4*)&bb[0] = *(const float4*)&sK[cur][k][tx * 8];
            *(float4*)&bb[4] = *(const float4*)&sK[cur][k][tx * 8 + 4];
#pragma unroll
            for (int i = 0; i < 8; i++)
#pragma unroll
                for (int j = 0; j < 8; j++) acc[i][j] += a[i] * bb[j];
        }
        if (kt + 1 < NK) {
            const int nx = cur ^ 1;
            *(float4*)&sQ[nx][lr][lc]     = q0;
            *(float4*)&sQ[nx][lr][lc + 4] = q1;
            *(float4*)&sK[nx][lr][lc]     = k0;
            *(float4*)&sK[nx][lr][lc + 4] = k1;
        }
        __syncthreads();
    }

    float mn = __int_as_float(0x7f800000);
#pragma unroll
    for (int i = 0; i < 8; i++) {
        const int n = n0 + ty * 8 + i;
        float4 r0 = make_float4(acc[i][0] * 0.125f, acc[i][1] * 0.125f,
                                acc[i][2] * 0.125f, acc[i][3] * 0.125f);
        float4 r1 = make_float4(acc[i][4] * 0.125f, acc[i][5] * 0.125f,
                                acc[i][6] * 0.125f, acc[i][7] * 0.125f);
        mn = fminf(mn, fminf(fminf(r0.x, r0.y), fminf(r0.z, r0.w)));
        mn = fminf(mn, fminf(fminf(r1.x, r1.y), fminf(r1.z, r1.w)));
        float* p = &g_s[((size_t)bh * NN + n) * NN + m0 + tx * 8];
        *(float4*)&p[0] = r0; *(float4*)&p[4] = r1;
    }
#pragma unroll
    for (int o = 16; o > 0; o >>= 1) mn = fminf(mn, __shfl_xor_sync(0xffffffffu, mn, o));
    if ((t & 31) == 0) sred[t >> 5] = mn;
    __syncthreads();
    if (t == 0) {
        float v = sred[0];
#pragma unroll
        for (int i = 1; i < 8; i++) v = fminf(v, sred[i]);
        atomicMin(&g_minenc, enc_f(v));
    }
}

// ---------------- output 2: mean over heads of masked scores ----------------
__global__ void __launch_bounds__(256)
out2_kernel(float* __restrict__ O2) {
    const int idx = blockIdx.x * 256 + threadIdx.x;
    const int total = BB * NN * NN / 4;
    if (idx >= total) return;
    const int e = idx * 4;
    const int m = e % NN;
    const int n = (e / NN) % NN;
    const int b = e / (NN * NN);

    float4 acc = make_float4(0.f, 0.f, 0.f, 0.f);
#pragma unroll
    for (int h = 0; h < HH; h++) {
        float4 s = *(const float4*)&g_s[((size_t)(b * HH + h) * NN + n) * NN + m];
        acc.x += s.x; acc.y += s.y; acc.z += s.z; acc.w += s.w;
    }
    const float pen = dec_f(g_minenc) - 20.0f;
    uchar4 mk = *(const uchar4*)&g_mask[(size_t)n * NN + m];
    acc.x = acc.x * 0.125f + (mk.x ? 0.f : pen);
    acc.y = acc.y * 0.125f + (mk.y ? 0.f : pen);
    acc.z = acc.z * 0.125f + (mk.z ? 0.f : pen);
    acc.w = acc.w * 0.125f + (mk.w ? 0.f : pen);
    *(float4*)&O2[e] = acc;
}

// ---------------- softmax (in place, scores -> probs) -----------------------
__global__ void __launch_bounds__(256)
softmax_kernel() {
    const int row = blockIdx.x;               // bh*NN + n
    const int n   = row % NN;
    float* S = g_s + (size_t)row * NN;
    const unsigned char* mrow = g_mask + (size_t)n * NN;
    const int tid = threadIdx.x;
    const float pen = dec_f(g_minenc) - 20.0f;

    __shared__ float sredA[8];
    __shared__ float sredB[8];

    float v[6];
    float mx = __int_as_float(0xff800000);
#pragma unroll
    for (int i = 0; i < 6; i++) {
        int m = tid + i * 256;
        float s = S[m];
        if (!mrow[m]) s += pen;
        v[i] = s;
        mx = fmaxf(mx, s);
    }
#pragma unroll
    for (int o = 16; o > 0; o >>= 1) mx = fmaxf(mx, __shfl_xor_sync(0xffffffffu, mx, o));
    if ((tid & 31) == 0) sredA[tid >> 5] = mx;
    __syncthreads();
    mx = sredA[0];
#pragma unroll
    for (int i = 1; i < 8; i++) mx = fmaxf(mx, sredA[i]);

    float sum = 0.f;
#pragma unroll
    for (int i = 0; i < 6; i++) {
        v[i] = __expf(v[i] - mx);
        sum += v[i];
    }
#pragma unroll
    for (int o = 16; o > 0; o >>= 1) sum += __shfl_xor_sync(0xffffffffu, sum, o);
    if ((tid & 31) == 0) sredB[tid >> 5] = sum;
    __syncthreads();
    sum = sredB[0];
#pragma unroll
    for (int i = 1; i < 8; i++) sum += sredB[i];
    const float inv = 1.0f / sum;
#pragma unroll
    for (int i = 0; i < 6; i++) S[tid + i * 256] = v[i] * inv;
}

// ---------------- PV: X[n,d] = sum_m P[n,m] V[d,m] -> g_x[b, d*8+h, n] ------
// 128(n) x 64(d) tile, 128 threads, 8x8 per thread, m-step 16 double buffered
__global__ void __launch_bounds__(128)
pv_kernel() {
    __shared__ float sP[2][16][128];  // [buf][m][n]
    __shared__ float sV[2][16][64];   // [buf][m][d]
    const int bh = blockIdx.y;
    const int n0 = blockIdx.x * 128;
    const int t  = threadIdx.x;
    const int tx = t & 7, ty = t >> 3;            // tx: d group (0..7), ty: n group (0..15)
    const float* P = g_s + (size_t)bh * NN * NN;
    const float* V = g_v + (size_t)bh * DH * NN;  // [d][m]

    const int vd = t >> 1, vm0 = (t & 1) * 8;     // V load map

    float pr[16];      // P prefetch: 16 contiguous floats of row n0+t
    float4 v0, v1;     // V prefetch
    {
        const float* prow = &P[(size_t)(n0 + t) * NN];
        *(float4*)&pr[0]  = *(const float4*)&prow[0];
        *(float4*)&pr[4]  = *(const float4*)&prow[4];
        *(float4*)&pr[8]  = *(const float4*)&prow[8];
        *(float4*)&pr[12] = *(const float4*)&prow[12];
        v0 = *(const float4*)&V[(size_t)vd * NN + vm0];
        v1 = *(const float4*)&V[(size_t)vd * NN + vm0 + 4];
    }
#pragma unroll
    for (int mi = 0; mi < 16; mi++) sP[0][mi][t] = pr[mi];
    sV[0][vm0 + 0][vd] = v0.x; sV[0][vm0 + 1][vd] = v0.y;
    sV[0][vm0 + 2][vd] = v0.z; sV[0][vm0 + 3][vd] = v0.w;
    sV[0][vm0 + 4][vd] = v1.x; sV[0][vm0 + 5][vd] = v1.y;
    sV[0][vm0 + 6][vd] = v1.z; sV[0][vm0 + 7][vd] = v1.w;
    __syncthreads();

    float acc[8][8] = {};
    const int NK = NN / 16;  // 96
    for (int mt = 0; mt < NK; mt++) {
        const int cur = mt & 1;
        if (mt + 1 < NK) {
            const int m0 = (mt + 1) * 16;
            const float* prow = &P[(size_t)(n0 + t) * NN + m0];
            *(float4*)&pr[0]  = *(const float4*)&prow[0];
            *(float4*)&pr[4]  = *(const float4*)&prow[4];
            *(float4*)&pr[8]  = *(const float4*)&prow[8];
            *(float4*)&pr[12] = *(const float4*)&prow[12];
            v0 = *(const float4*)&V[(size_t)vd * NN + m0 + vm0];
            v1 = *(const float4*)&V[(size_t)vd * NN + m0 + vm0 + 4];
        }
#pragma unroll
        for (int m = 0; m < 16; m++) {
            float a[8], bb[8];
            *(float4*)&a[0]  = *(const float4*)&sP[cur][m][ty * 8];
            *(float4*)&a[4]  = *(const float4*)&sP[cur][m][ty * 8 + 4];
            *(float4*)&bb[0] = *(const float4*)&sV[cur][m][tx * 8];
            *(float4*)&bb[4] = *(const float4*)&sV[cur][m][tx * 8 + 4];
#pragma unroll
            for (int i = 0; i < 8; i++)
#pragma unroll
                for (int j = 0; j < 8; j++) acc[i][j] += a[i] * bb[j];
        }
        if (mt + 1 < NK) {
            const int nx = cur ^ 1;
#pragma unroll
            for (int mi = 0; mi < 16; mi++) sP[nx][mi][t] = pr[mi];
            sV[nx][vm0 + 0][vd] = v0.x; sV[nx][vm0 + 1][vd] = v0.y;
            sV[nx][vm0 + 2][vd] = v0.z; sV[nx][vm0 + 3][vd] = v0.w;
            sV[nx][vm0 + 4][vd] = v1.x; sV[nx][vm0 + 5][vd] = v1.y;
            sV[nx][vm0 + 6][vd] = v1.z; sV[nx][vm0 + 7][vd] = v1.w;
        }
        __syncthreads();
    }

    const int b = bh >> 3, h = bh & 7;
#pragma unroll
    for (int j = 0; j < 8; j++) {
        const int d = tx * 8 + j;
        const int c = d * 8 + h;
        float* p = &g_x[((size_t)b * DD + c) * NN + n0 + ty * 8];
        *(float4*)&p[0] = make_float4(acc[0][j], acc[1][j], acc[2][j], acc[3][j]);
        *(float4*)&p[4] = make_float4(acc[4][j], acc[5][j], acc[6][j], acc[7][j]);
    }
}

// ---------------- launch ----------------------------------------------------
extern "C" void kernel_launch(void* const* d_in, const int* in_sizes, int n_in,
                              void* d_out, int out_size) {
    const float* query = (const float*)d_in[0];
    const float* key   = (const float*)d_in[1];
    const float* value = (const float*)d_in[2];
    // d_in[3] = dist (unused)
    const void* mask   = d_in[4];
    const float* Wq = (const float*)d_in[5];
    const float* bq = (const float*)d_in[6];
    const float* Wk = (const float*)d_in[7];
    const float* bk = (const float*)d_in[8];
    const float* Wv = (const float*)d_in[9];
    const float* bv = (const float*)d_in[10];
    const float* Wm = (const float*)d_in[11];
    const float* bm = (const float*)d_in[12];

    float* out  = (float*)d_out;                         // [B, D, N]
    float* out2 = out + (size_t)BB * DD * NN;            // [B, N, N]

    float *pq, *pk, *pv, *px;
    cudaGetSymbolAddress((void**)&pq, g_q);
    cudaGetSymbolAddress((void**)&pk, g_k);
    cudaGetSymbolAddress((void**)&pv, g_v);
    cudaGetSymbolAddress((void**)&px, g_x);

    init_kernel<<<1, 1>>>();

    mask_classify_kernel<<<256, 256>>>((const unsigned*)mask);
    mask_convert_kernel<<<256, 256>>>(mask);

    dim3 gproj(NN / 128, DD / 64, BB);   // 12 x 8 x 4
    proj_kernel<1><<<gproj, 128>>>(query, Wq, bq, pq);
    proj_kernel<1><<<gproj, 128>>>(key,   Wk, bk, pk);
    proj_kernel<1><<<gproj, 128>>>(value, Wv, bv, pv);

    scores_kernel<<<dim3(NN / 128, NN / 128, BB * HH), 256>>>();

    {
        int total4 = BB * NN * NN / 4;
        out2_kernel<<<(total4 + 255) / 256, 256>>>(out2);
    }

    softmax_kernel<<<BB * HH * NN, 256>>>();

    pv_kernel<<<dim3(NN / 128, BB * HH), 128>>>();

    proj_kernel<0><<<gproj, 128>>>(px, Wm, bm, out);
}

// round 5
// speedup vs baseline: 1.2286x; 1.2286x over previous
#include <cuda_runtime.h>
#include <cuda_bf16.h>
#include <cstdint>

#define BB 4
#define DD 512
#define NN 1536
#define HH 8
#define DH 64
#define PS 40   // smem row stride in halves (k + 8 pad -> conflict-free ldmatrix)

// ---------------- scratch ----------------------------------------------------
__device__ unsigned g_q[(size_t)BB * HH * DH * NN];   // packed bf16 (hi,lo), [b,h,d,n]
__device__ unsigned g_k[(size_t)BB * HH * DH * NN];   // packed bf16 (hi,lo), [b,h,d,n]
__device__ unsigned g_v[(size_t)BB * HH * DH * NN];   // packed bf16 (hi,lo), [b,h,d,n]
__device__ float    g_s[(size_t)BB * HH * NN * NN];   // fp32 scores -> packed probs (in place)
__device__ float    g_x[(size_t)BB * DD * NN];        // fp32 [b,c,n]
__device__ unsigned char g_mask[(size_t)NN * NN];
__device__ unsigned g_minenc;
__device__ unsigned g_maskflags;

// ---------------- helpers ----------------------------------------------------
__device__ __forceinline__ unsigned enc_f(float x) {
    unsigned b = __float_as_uint(x);
    return (b & 0x80000000u) ? ~b : (b | 0x80000000u);
}
__device__ __forceinline__ float dec_f(unsigned e) {
    return (e & 0x80000000u) ? __uint_as_float(e ^ 0x80000000u)
                             : __uint_as_float(~e);
}

// fp32 -> (bf16 hi, bf16 lo) packed into one u32 (hi in low half)
__device__ __forceinline__ unsigned f2pair(float x) {
    __nv_bfloat16 h = __float2bfloat16(x);
    float hf = __bfloat162float(h);
    __nv_bfloat16 l = __float2bfloat16(x - hf);
    return (unsigned)__bfloat16_as_ushort(h) | ((unsigned)__bfloat16_as_ushort(l) << 16);
}

__device__ __forceinline__ void ldm4(unsigned& r0, unsigned& r1, unsigned& r2, unsigned& r3,
                                     unsigned addr) {
    asm volatile("ldmatrix.sync.aligned.m8n8.x4.shared.b16 {%0,%1,%2,%3}, [%4];"
                 : "=r"(r0), "=r"(r1), "=r"(r2), "=r"(r3) : "r"(addr));
}

__device__ __forceinline__ void mma16816(float* c, unsigned a0, unsigned a1, unsigned a2,
                                         unsigned a3, unsigned b0, unsigned b1) {
    asm volatile("mma.sync.aligned.m16n8k16.row.col.f32.bf16.bf16.f32 "
                 "{%0,%1,%2,%3}, {%4,%5,%6,%7}, {%8,%9}, {%0,%1,%2,%3};"
                 : "+f"(c[0]), "+f"(c[1]), "+f"(c[2]), "+f"(c[3])
                 : "r"(a0), "r"(a1), "r"(a2), "r"(a3), "r"(b0), "r"(b1));
}

// ldmatrix lane address into a [rows][PS] ushort smem array
__device__ __forceinline__ unsigned ldm_addr(unsigned base, int lane, int row0, int col0) {
    int r = row0 + (lane & 7) + ((lane >> 3) & 1) * 8;
    int c = col0 + (lane >> 4) * 8;
    return base + (unsigned)(r * PS + c) * 2u;
}

// One k16 step of split-bf16 MMA: acc += Ah*Bh + Ah*Bl + Al*Bh
// A: IM m16 tiles starting at mBase; B: 4 n8 tiles starting at nBase.
template <int IM>
__device__ __forceinline__ void mma_step(float (*acc)[4][4],
                                         unsigned baAh, unsigned baAl,
                                         unsigned baBh, unsigned baBl,
                                         int lane, int mBase, int nBase, int kk) {
    unsigned A[IM][4], B[4][2], C[4][2];
    unsigned x0, x1, x2, x3;
#pragma unroll
    for (int im = 0; im < IM; im++)
        ldm4(A[im][0], A[im][1], A[im][2], A[im][3],
             ldm_addr(baAh, lane, mBase + im * 16, kk));
    ldm4(x0, x1, x2, x3, ldm_addr(baBh, lane, nBase, kk));
    B[0][0] = x0; B[0][1] = x2; B[1][0] = x1; B[1][1] = x3;
    ldm4(x0, x1, x2, x3, ldm_addr(baBh, lane, nBase + 16, kk));
    B[2][0] = x0; B[2][1] = x2; B[3][0] = x1; B[3][1] = x3;
#pragma unroll
    for (int im = 0; im < IM; im++)
#pragma unroll
        for (int jn = 0; jn < 4; jn++)
            mma16816(acc[im][jn], A[im][0], A[im][1], A[im][2], A[im][3], B[jn][0], B[jn][1]);
    ldm4(x0, x1, x2, x3, ldm_addr(baBl, lane, nBase, kk));
    C[0][0] = x0; C[0][1] = x2; C[1][0] = x1; C[1][1] = x3;
    ldm4(x0, x1, x2, x3, ldm_addr(baBl, lane, nBase + 16, kk));
    C[2][0] = x0; C[2][1] = x2; C[3][0] = x1; C[3][1] = x3;
#pragma unroll
    for (int im = 0; im < IM; im++)
#pragma unroll
        for (int jn = 0; jn < 4; jn++)
            mma16816(acc[im][jn], A[im][0], A[im][1], A[im][2], A[im][3], C[jn][0], C[jn][1]);
#pragma unroll
    for (int im = 0; im < IM; im++)
        ldm4(A[im][0], A[im][1], A[im][2], A[im][3],
             ldm_addr(baAl, lane, mBase + im * 16, kk));
#pragma unroll
    for (int im = 0; im < IM; im++)
#pragma unroll
        for (int jn = 0; jn < 4; jn++)
            mma16816(acc[im][jn], A[im][0], A[im][1], A[im][2], A[im][3], B[jn][0], B[jn][1]);
}

__global__ void init_kernel() { g_minenc = 0xFFFFFFFFu; g_maskflags = 0u; }

// ---------------- mask dtype classification + normalization -----------------
__global__ void __launch_bounds__(256)
mask_classify_kernel(const unsigned* __restrict__ mw) {
    const int total = NN * NN / 4;
    unsigned local = 0;
    for (int i = blockIdx.x * 256 + threadIdx.x; i < total; i += gridDim.x * 256) {
        unsigned w = mw[i];
        if (w != 0u && w != 1u)          local |= 1u;
        if (w != 0u && w != 0x3f800000u) local |= 2u;
    }
#pragma unroll
    for (int o = 16; o > 0; o >>= 1) local |= __shfl_xor_sync(0xffffffffu, local, o);
    if ((threadIdx.x & 31) == 0 && local) atomicOr(&g_maskflags, local);
}

__global__ void __launch_bounds__(256)
mask_convert_kernel(const void* __restrict__ mraw) {
    const unsigned f = g_maskflags;
    const int mode = ((f & 2u) == 0u) ? 2 : (((f & 1u) == 0u) ? 1 : 0);
    const int total = NN * NN;
    if (mode == 0) {
        const unsigned char* m8 = (const unsigned char*)mraw;
        for (int i = blockIdx.x * 256 + threadIdx.x; i < total; i += gridDim.x * 256)
            g_mask[i] = m8[i] ? 1 : 0;
    } else if (mode == 1) {
        const int* mi = (const int*)mraw;
        for (int i = blockIdx.x * 256 + threadIdx.x; i < total; i += gridDim.x * 256)
            g_mask[i] = mi[i] ? 1 : 0;
    } else {
        const float* mf = (const float*)mraw;
        for (int i = blockIdx.x * 256 + threadIdx.x; i < total; i += gridDim.x * 256)
            g_mask[i] = (mf[i] != 0.0f) ? 1 : 0;
    }
}

// ---------------- projection: Y[b,o,n] = sum_c W[o,c] X[b,c,n] + bias[o] ----
// block 64(o) x 128(n), 256 thr, kc=32, split-bf16 mma.
// MODE 0: fp32 out [b,o,n]; MODE 1: packed pairs [b,h,d,n]
template <int MODE>
__global__ void __launch_bounds__(256)
proj_kernel(const float* __restrict__ X, const float* __restrict__ W,
            const float* __restrict__ bias, void* __restrict__ Yv) {
    __shared__ unsigned short sWh[64][PS], sWl[64][PS];
    __shared__ unsigned short sXh[128][PS], sXl[128][PS];
    const int b  = blockIdx.z;
    const int o0 = blockIdx.y * 64;
    const int n0 = blockIdx.x * 128;
    const int t  = threadIdx.x;
    const int lane = t & 31, w = t >> 5;
    const int wm = w & 1, wn = w >> 1;          // warp tile 32(o) x 32(n)
    const float* Xb = X + (size_t)b * DD * NN;

    const int wr = t >> 2, wf = t & 3;          // W: row, f4 col
    const int xc = t >> 3, xf = t & 7;          // X: c row, f4 n col

    const unsigned baWh = (unsigned)__cvta_generic_to_shared(&sWh[0][0]);
    const unsigned baWl = (unsigned)__cvta_generic_to_shared(&sWl[0][0]);
    const unsigned baXh = (unsigned)__cvta_generic_to_shared(&sXh[0][0]);
    const unsigned baXl = (unsigned)__cvta_generic_to_shared(&sXl[0][0]);

    float4 pw[2], px[4];
    float acc[2][4][4];
#pragma unroll
    for (int i = 0; i < 2; i++)
#pragma unroll
        for (int j = 0; j < 4; j++)
#pragma unroll
            for (int k = 0; k < 4; k++) acc[i][j][k] = 0.f;

    auto load_regs = [&](int c0) {
        pw[0] = *(const float4*)&W[(size_t)(o0 + wr) * DD + c0 + wf * 4];
        pw[1] = *(const float4*)&W[(size_t)(o0 + wr) * DD + c0 + 16 + wf * 4];
#pragma unroll
        for (int i = 0; i < 4; i++)
            px[i] = *(const float4*)&Xb[(size_t)(c0 + xc) * NN + n0 + (xf + i * 8) * 4];
    };
    auto store_smem = [&]() {
#pragma unroll
        for (int g = 0; g < 2; g++) {
            const float* f = (const float*)&pw[g];
#pragma unroll
            for (int j = 0; j < 4; j++) {
                unsigned p = f2pair(f[j]);
                int c = g * 16 + wf * 4 + j;
                sWh[wr][c] = (unsigned short)p;
                sWl[wr][c] = (unsigned short)(p >> 16);
            }
        }
#pragma unroll
        for (int i = 0; i < 4; i++) {
            const float* f = (const float*)&px[i];
#pragma unroll
            for (int j = 0; j < 4; j++) {
                unsigned p = f2pair(f[j]);
                int nl = (xf + i * 8) * 4 + j;
                sXh[nl][xc] = (unsigned short)p;
                sXl[nl][xc] = (unsigned short)(p >> 16);
            }
        }
    };

    load_regs(0); store_smem(); __syncthreads();
    const int NC = DD / 32;
    for (int c = 0; c < NC; c++) {
        if (c + 1 < NC) load_regs((c + 1) * 32);
        mma_step<2>(acc, baWh, baWl, baXh, baXl, lane, wm * 32, wn * 32, 0);
        mma_step<2>(acc, baWh, baWl, baXh, baXl, lane, wm * 32, wn * 32, 16);
        if (c + 1 < NC) { __syncthreads(); store_smem(); __syncthreads(); }
    }

#pragma unroll
    for (int im = 0; im < 2; im++) {
        const int ob = o0 + wm * 32 + im * 16 + (lane >> 2);
        const float bs0 = bias[ob], bs1 = bias[ob + 8];
#pragma unroll
        for (int jn = 0; jn < 4; jn++) {
            float* cc = acc[im][jn];
            const int n = n0 + wn * 32 + jn * 8 + 2 * (lane & 3);
            if (MODE == 0) {
                float* Y = (float*)Yv;
                *(float2*)&Y[((size_t)b * DD + ob) * NN + n]     = make_float2(cc[0] + bs0, cc[1] + bs0);
                *(float2*)&Y[((size_t)b * DD + ob + 8) * NN + n] = make_float2(cc[2] + bs1, cc[3] + bs1);
            } else {
                unsigned* Y = (unsigned*)Yv;
                int o = ob, h = o & 7, d = o >> 3;
                *(uint2*)&Y[(((size_t)b * HH + h) * DH + d) * NN + n] =
                    make_uint2(f2pair(cc[0] + bs0), f2pair(cc[1] + bs0));
                o = ob + 8; h = o & 7; d = o >> 3;
                *(uint2*)&Y[(((size_t)b * HH + h) * DH + d) * NN + n] =
                    make_uint2(f2pair(cc[2] + bs1), f2pair(cc[3] + bs1));
            }
        }
    }
}

// ---------------- scores: S[bh,n,m] = (1/8) sum_d Q[d,n] K[d,m] -------------
// block 128(n) x 128(m), 256 thr, kc=32 (2 chunks), split-bf16 mma.
__global__ void __launch_bounds__(256)
scores_kernel() {
    __shared__ unsigned short sQh[128][PS], sQl[128][PS];
    __shared__ unsigned short sKh[128][PS], sKl[128][PS];
    __shared__ float sred[8];
    const int bh = blockIdx.z;
    const int n0 = blockIdx.y * 128;
    const int m0 = blockIdx.x * 128;
    const int t  = threadIdx.x;
    const int lane = t & 31, w = t >> 5;
    const int wm = w & 1, wn = w >> 1;          // warp tile 64(n) x 32(m)
    const unsigned* Q = g_q + (size_t)bh * DH * NN;
    const unsigned* K = g_k + (size_t)bh * DH * NN;

    const int dr = t >> 3, cf = t & 7;          // d row (0..31), f4 col base

    const unsigned baQh = (unsigned)__cvta_generic_to_shared(&sQh[0][0]);
    const unsigned baQl = (unsigned)__cvta_generic_to_shared(&sQl[0][0]);
    const unsigned baKh = (unsigned)__cvta_generic_to_shared(&sKh[0][0]);
    const unsigned baKl = (unsigned)__cvta_generic_to_shared(&sKl[0][0]);

    uint4 pq[4], pk[4];
    float acc[4][4][4];
#pragma unroll
    for (int i = 0; i < 4; i++)
#pragma unroll
        for (int j = 0; j < 4; j++)
#pragma unroll
            for (int k = 0; k < 4; k++) acc[i][j][k] = 0.f;

    auto load_regs = [&](int d0) {
#pragma unroll
        for (int i = 0; i < 4; i++) {
            pq[i] = *(const uint4*)&Q[(size_t)(d0 + dr) * NN + n0 + (cf + i * 8) * 4];
            pk[i] = *(const uint4*)&K[(size_t)(d0 + dr) * NN + m0 + (cf + i * 8) * 4];
        }
    };
    auto store_smem = [&]() {
#pragma unroll
        for (int i = 0; i < 4; i++) {
            const unsigned* q = (const unsigned*)&pq[i];
            const unsigned* k = (const unsigned*)&pk[i];
#pragma unroll
            for (int j = 0; j < 4; j++) {
                int rl = (cf + i * 8) * 4 + j;
                sQh[rl][dr] = (unsigned short)q[j];
                sQl[rl][dr] = (unsigned short)(q[j] >> 16);
                sKh[rl][dr] = (unsigned short)k[j];
                sKl[rl][dr] = (unsigned short)(k[j] >> 16);
            }
        }
    };

    load_regs(0); store_smem(); __syncthreads();
    for (int c = 0; c < 2; c++) {
        if (c + 1 < 2) load_regs(32);
        mma_step<4>(acc, baQh, baQl, baKh, baKl, lane, wm * 64, wn * 32, 0);
        mma_step<4>(acc, baQh, baQl, baKh, baKl, lane, wm * 64, wn * 32, 16);
        if (c + 1 < 2) { __syncthreads(); store_smem(); __syncthreads(); }
    }

    float mn = __int_as_float(0x7f800000);
#pragma unroll
    for (int im = 0; im < 4; im++) {
        const int n = n0 + wm * 64 + im * 16 + (lane >> 2);
#pragma unroll
        for (int jn = 0; jn < 4; jn++) {
            float* cc = acc[im][jn];
            const int m = m0 + wn * 32 + jn * 8 + 2 * (lane & 3);
            float2 r0 = make_float2(cc[0] * 0.125f, cc[1] * 0.125f);
            float2 r1 = make_float2(cc[2] * 0.125f, cc[3] * 0.125f);
            mn = fminf(mn, fminf(fminf(r0.x, r0.y), fminf(r1.x, r1.y)));
            *(float2*)&g_s[((size_t)bh * NN + n) * NN + m]       = r0;
            *(float2*)&g_s[((size_t)bh * NN + n + 8) * NN + m]   = r1;
        }
    }
#pragma unroll
    for (int o = 16; o > 0; o >>= 1) mn = fminf(mn, __shfl_xor_sync(0xffffffffu, mn, o));
    if (lane == 0) sred[w] = mn;
    __syncthreads();
    if (t == 0) {
        float v = sred[0];
#pragma unroll
        for (int i = 1; i < 8; i++) v = fminf(v, sred[i]);
        atomicMin(&g_minenc, enc_f(v));
    }
}

// ---------------- output 2: mean over heads of masked scores ----------------
__global__ void __launch_bounds__(256)
out2_kernel(float* __restrict__ O2) {
    const int idx = blockIdx.x * 256 + threadIdx.x;
    const int total = BB * NN * NN / 4;
    if (idx >= total) return;
    const int e = idx * 4;
    const int m = e % NN;
    const int n = (e / NN) % NN;
    const int b = e / (NN * NN);

    float4 acc = make_float4(0.f, 0.f, 0.f, 0.f);
#pragma unroll
    for (int h = 0; h < HH; h++) {
        float4 s = *(const float4*)&g_s[((size_t)(b * HH + h) * NN + n) * NN + m];
        acc.x += s.x; acc.y += s.y; acc.z += s.z; acc.w += s.w;
    }
    const float pen = dec_f(g_minenc) - 20.0f;
    uchar4 mk = *(const uchar4*)&g_mask[(size_t)n * NN + m];
    acc.x = acc.x * 0.125f + (mk.x ? 0.f : pen);
    acc.y = acc.y * 0.125f + (mk.y ? 0.f : pen);
    acc.z = acc.z * 0.125f + (mk.z ? 0.f : pen);
    acc.w = acc.w * 0.125f + (mk.w ? 0.f : pen);
    *(float4*)&O2[e] = acc;
}

// ---------------- softmax (in place; writes packed bf16-pair probs) ---------
__global__ void __launch_bounds__(256)
softmax_kernel() {
    const int row = blockIdx.x;               // bh*NN + n
    const int n   = row % NN;
    float* S = g_s + (size_t)row * NN;
    unsigned* Su = (unsigned*)S;
    const unsigned char* mrow = g_mask + (size_t)n * NN;
    const int tid = threadIdx.x;
    const float pen = dec_f(g_minenc) - 20.0f;

    __shared__ float sredA[8];
    __shared__ float sredB[8];

    float v[6];
    float mx = __int_as_float(0xff800000);
#pragma unroll
    for (int i = 0; i < 6; i++) {
        int m = tid + i * 256;
        float s = S[m];
        if (!mrow[m]) s += pen;
        v[i] = s;
        mx = fmaxf(mx, s);
    }
#pragma unroll
    for (int o = 16; o > 0; o >>= 1) mx = fmaxf(mx, __shfl_xor_sync(0xffffffffu, mx, o));
    if ((tid & 31) == 0) sredA[tid >> 5] = mx;
    __syncthreads();
    mx = sredA[0];
#pragma unroll
    for (int i = 1; i < 8; i++) mx = fmaxf(mx, sredA[i]);

    float sum = 0.f;
#pragma unroll
    for (int i = 0; i < 6; i++) {
        v[i] = __expf(v[i] - mx);
        sum += v[i];
    }
#pragma unroll
    for (int o = 16; o > 0; o >>= 1) sum += __shfl_xor_sync(0xffffffffu, sum, o);
    if ((tid & 31) == 0) sredB[tid >> 5] = sum;
    __syncthreads();
    sum = sredB[0];
#pragma unroll
    for (int i = 1; i < 8; i++) sum += sredB[i];
    const float inv = 1.0f / sum;
#pragma unroll
    for (int i = 0; i < 6; i++) Su[tid + i * 256] = f2pair(v[i] * inv);
}

// ---------------- PV: x[n,d] = sum_m P[n,m] V[d,m] -> g_x[b, d*8+h, n] ------
// block 128(n) x 64(d), 256 thr, kc=32 over m (48 chunks), split-bf16 mma.
__global__ void __launch_bounds__(256)
pv_kernel() {
    __shared__ unsigned short sPh[128][PS], sPl[128][PS];
    __shared__ unsigned short sVh[64][PS], sVl[64][PS];
    const int bh = blockIdx.y;
    const int n0 = blockIdx.x * 128;
    const int t  = threadIdx.x;
    const int lane = t & 31, w = t >> 5;
    const int wm = w >> 1, wn = w & 1;          // warp tile 32(n) x 32(d)
    const unsigned* P = (const unsigned*)g_s + (size_t)bh * NN * NN;
    const unsigned* V = g_v + (size_t)bh * DH * NN;

    const int pr = t >> 1, pf = t & 1;          // P: n row, f4 group
    const int vr = t >> 2, vf = t & 3;          // V: d row, f4 group

    const unsigned baPh = (unsigned)__cvta_generic_to_shared(&sPh[0][0]);
    const unsigned baPl = (unsigned)__cvta_generic_to_shared(&sPl[0][0]);
    const unsigned baVh = (unsigned)__cvta_generic_to_shared(&sVh[0][0]);
    const unsigned baVl = (unsigned)__cvta_generic_to_shared(&sVl[0][0]);

    uint4 pp[4], pv[2];
    float acc[2][4][4];
#pragma unroll
    for (int i = 0; i < 2; i++)
#pragma unroll
        for (int j = 0; j < 4; j++)
#pragma unroll
            for (int k = 0; k < 4; k++) acc[i][j][k] = 0.f;

    auto load_regs = [&](int m0) {
#pragma unroll
        for (int i = 0; i < 4; i++)
            pp[i] = *(const uint4*)&P[(size_t)(n0 + pr) * NN + m0 + (pf * 4 + i) * 4];
#pragma unroll
        for (int i = 0; i < 2; i++)
            pv[i] = *(const uint4*)&V[(size_t)vr * NN + m0 + (vf + i * 4) * 4];
    };
    auto store_smem = [&]() {
#pragma unroll
        for (int i = 0; i < 4; i++) {
            const unsigned* p = (const unsigned*)&pp[i];
#pragma unroll
            for (int j = 0; j < 4; j++) {
                int ml = (pf * 4 + i) * 4 + j;
                sPh[pr][ml] = (unsigned short)p[j];
                sPl[pr][ml] = (unsigned short)(p[j] >> 16);
            }
        }
#pragma unroll
        for (int i = 0; i < 2; i++) {
            const unsigned* p = (const unsigned*)&pv[i];
#pragma unroll
            for (int j = 0; j < 4; j++) {
                int ml = (vf + i * 4) * 4 + j;
                sVh[vr][ml] = (unsigned short)p[j];
                sVl[vr][ml] = (unsigned short)(p[j] >> 16);
            }
        }
    };

    load_regs(0); store_smem(); __syncthreads();
    const int NC = NN / 32;
    for (int c = 0; c < NC; c++) {
        if (c + 1 < NC) load_regs((c + 1) * 32);
        mma_step<2>(acc, baPh, baPl, baVh, baVl, lane, wm * 32, wn * 32, 0);
        mma_step<2>(acc, baPh, baPl, baVh, baVl, lane, wm * 32, wn * 32, 16);
        if (c + 1 < NC) { __syncthreads(); store_smem(); __syncthreads(); }
    }

    const int b = bh >> 3, h = bh & 7;
#pragma unroll
    for (int im = 0; im < 2; im++) {
        const int n = n0 + wm * 32 + im * 16 + (lane >> 2);
#pragma unroll
        for (int jn = 0; jn < 4; jn++) {
            float* cc = acc[im][jn];
            const int d = wn * 32 + jn * 8 + 2 * (lane & 3);
            g_x[((size_t)b * DD + (d * 8 + h)) * NN + n]           = cc[0];
            g_x[((size_t)b * DD + ((d + 1) * 8 + h)) * NN + n]     = cc[1];
            g_x[((size_t)b * DD + (d * 8 + h)) * NN + n + 8]       = cc[2];
            g_x[((size_t)b * DD + ((d + 1) * 8 + h)) * NN + n + 8] = cc[3];
        }
    }
}

// ---------------- launch ----------------------------------------------------
extern "C" void kernel_launch(void* const* d_in, const int* in_sizes, int n_in,
                              void* d_out, int out_size) {
    const float* query = (const float*)d_in[0];
    const float* key   = (const float*)d_in[1];
    const float* value = (const float*)d_in[2];
    // d_in[3] = dist (unused)
    const void* mask   = d_in[4];
    const float* Wq = (const float*)d_in[5];
    const float* bq = (const float*)d_in[6];
    const float* Wk = (const float*)d_in[7];
    const float* bk = (const float*)d_in[8];
    const float* Wv = (const float*)d_in[9];
    const float* bv = (const float*)d_in[10];
    const float* Wm = (const float*)d_in[11];
    const float* bm = (const float*)d_in[12];

    float* out  = (float*)d_out;                         // [B, D, N]
    float* out2 = out + (size_t)BB * DD * NN;            // [B, N, N]

    void *pq, *pk, *pv, *px;
    cudaGetSymbolAddress(&pq, g_q);
    cudaGetSymbolAddress(&pk, g_k);
    cudaGetSymbolAddress(&pv, g_v);
    cudaGetSymbolAddress(&px, g_x);

    init_kernel<<<1, 1>>>();
    mask_classify_kernel<<<256, 256>>>((const unsigned*)mask);
    mask_convert_kernel<<<256, 256>>>(mask);

    dim3 gproj(NN / 128, DD / 64, BB);   // 12 x 8 x 4
    proj_kernel<1><<<gproj, 256>>>(query, Wq, bq, pq);
    proj_kernel<1><<<gproj, 256>>>(key,   Wk, bk, pk);
    proj_kernel<1><<<gproj, 256>>>(value, Wv, bv, pv);

    scores_kernel<<<dim3(NN / 128, NN / 128, BB * HH), 256>>>();

    {
        int total4 = BB * NN * NN / 4;
        out2_kernel<<<(total4 + 255) / 256, 256>>>(out2);
    }

    softmax_kernel<<<BB * HH * NN, 256>>>();

    pv_kernel<<<dim3(NN / 128, BB * HH), 256>>>();

    proj_kernel<0><<<gproj, 256>>>((const float*)px, Wm, bm, out);
}

// round 7
// speedup vs baseline: 1.4784x; 1.2033x over previous
#include <cuda_runtime.h>
#include <cuda_bf16.h>
#include <cstdint>

#define BB 4
#define DD 512
#define NN 1536
#define HH 8
#define DH 64
#define PS 40   // smem row stride in halves (32 k + 8 pad -> conflict-free ldmatrix)

typedef unsigned short u16;
typedef unsigned int   u32;

// ---------------- scratch (device globals) -----------------------------------
__device__ __align__(16) u16 g_ith[(size_t)3 * BB * NN * DD];  // inputs^T hi [which][b][n][c]
__device__ __align__(16) u16 g_itl[(size_t)3 * BB * NN * DD];  // inputs^T lo
__device__ __align__(16) u16 g_wh[(size_t)4 * DD * DD];        // weights hi [which][o][c]
__device__ __align__(16) u16 g_wl[(size_t)4 * DD * DD];
__device__ __align__(16) u16 g_qh[(size_t)BB * HH * NN * DH];  // [b,h,n,d]
__device__ __align__(16) u16 g_ql[(size_t)BB * HH * NN * DH];
__device__ __align__(16) u16 g_kh[(size_t)BB * HH * NN * DH];  // [b,h,m,d]
__device__ __align__(16) u16 g_kl[(size_t)BB * HH * NN * DH];
__device__ __align__(16) u16 g_vh[(size_t)BB * HH * DH * NN];  // [b,h,d,m]
__device__ __align__(16) u16 g_vl[(size_t)BB * HH * DH * NN];
__device__ float g_s[(size_t)BB * HH * NN * NN];   // fp32 scores -> in-place split planes
__device__ __align__(16) u16 g_xth[(size_t)BB * NN * DD];      // PV out^T hi [b][n][c]
__device__ __align__(16) u16 g_xtl[(size_t)BB * NN * DD];
__device__ unsigned char g_mask[(size_t)NN * NN];
__device__ u32 g_minenc;
__device__ u32 g_maskflags;

// ---------------- helpers ----------------------------------------------------
__device__ __forceinline__ u32 enc_f(float x) {
    u32 b = __float_as_uint(x);
    return (b & 0x80000000u) ? ~b : (b | 0x80000000u);
}
__device__ __forceinline__ float dec_f(u32 e) {
    return (e & 0x80000000u) ? __uint_as_float(e ^ 0x80000000u)
                             : __uint_as_float(~e);
}
__device__ __forceinline__ u16 b16hi(float x) {
    return __bfloat16_as_ushort(__float2bfloat16(x));
}
__device__ __forceinline__ u16 b16lo(float x) {
    float hf = __bfloat162float(__float2bfloat16(x));
    return __bfloat16_as_ushort(__float2bfloat16(x - hf));
}

__global__ void init_kernel() { g_minenc = 0xFFFFFFFFu; g_maskflags = 0u; }

// ---------------- mask dtype classification + normalization ------------------
__global__ void __launch_bounds__(256)
mask_classify_kernel(const u32* __restrict__ mw) {
    const int total = NN * NN / 4;
    u32 local = 0;
    for (int i = blockIdx.x * 256 + threadIdx.x; i < total; i += gridDim.x * 256) {
        u32 w = mw[i];
        if (w != 0u && w != 1u)          local |= 1u;
        if (w != 0u && w != 0x3f800000u) local |= 2u;
    }
#pragma unroll
    for (int o = 16; o > 0; o >>= 1) local |= __shfl_xor_sync(0xffffffffu, local, o);
    if ((threadIdx.x & 31) == 0 && local) atomicOr(&g_maskflags, local);
}

__global__ void __launch_bounds__(256)
mask_convert_kernel(const void* __restrict__ mraw) {
    const u32 f = g_maskflags;
    const int mode = ((f & 2u) == 0u) ? 2 : (((f & 1u) == 0u) ? 1 : 0);
    const int total = NN * NN;
    if (mode == 0) {
        const unsigned char* m8 = (const unsigned char*)mraw;
        for (int i = blockIdx.x * 256 + threadIdx.x; i < total; i += gridDim.x * 256)
            g_mask[i] = m8[i] ? 1 : 0;
    } else if (mode == 1) {
        const int* mi = (const int*)mraw;
        for (int i = blockIdx.x * 256 + threadIdx.x; i < total; i += gridDim.x * 256)
            g_mask[i] = mi[i] ? 1 : 0;
    } else {
        const float* mf = (const float*)mraw;
        for (int i = blockIdx.x * 256 + threadIdx.x; i < total; i += gridDim.x * 256)
            g_mask[i] = (mf[i] != 0.0f) ? 1 : 0;
    }
}

// ---------------- prepasses: split inputs/weights into bf16 planes -----------
// inputs [b,c,n] fp32 -> transposed planes [which][b][n][c] hi/lo
__global__ void __launch_bounds__(256)
presplit_in_kernel(const float* __restrict__ q, const float* __restrict__ k,
                   const float* __restrict__ v) {
    __shared__ float tile[32][33];
    const int which = blockIdx.z >> 2, b = blockIdx.z & 3;
    const float* src = (which == 0 ? q : which == 1 ? k : v) + (size_t)b * DD * NN;
    const int n0 = blockIdx.x * 32, c0 = blockIdx.y * 32;
    const int tx = threadIdx.x, ty = threadIdx.y;  // 32 x 8
#pragma unroll
    for (int i = 0; i < 32; i += 8)
        tile[ty + i][tx] = src[(size_t)(c0 + ty + i) * NN + n0 + tx];
    __syncthreads();
    u16* dh = g_ith + (size_t)(which * BB + b) * NN * DD;
    u16* dl = g_itl + (size_t)(which * BB + b) * NN * DD;
#pragma unroll
    for (int i = 0; i < 32; i += 8) {
        float x = tile[tx][ty + i];
        size_t o = (size_t)(n0 + ty + i) * DD + c0 + tx;
        dh[o] = b16hi(x);
        dl[o] = b16lo(x);
    }
}

__global__ void __launch_bounds__(256)
presplit_w_kernel(const float* __restrict__ Wq, const float* __restrict__ Wk,
                  const float* __restrict__ Wv, const float* __restrict__ Wm) {
    const int total = 4 * DD * DD;
    for (int i = blockIdx.x * 256 + threadIdx.x; i < total; i += gridDim.x * 256) {
        int w = i >> 18;                 // DD*DD = 2^18
        int r = i & (DD * DD - 1);
        const float* src = (w == 0 ? Wq : w == 1 ? Wk : w == 2 ? Wv : Wm);
        float x = src[r];
        g_wh[i] = b16hi(x);
        g_wl[i] = b16lo(x);
    }
}

// ---------------- mma.sync machinery -----------------------------------------
__device__ __forceinline__ void ldm4(u32& r0, u32& r1, u32& r2, u32& r3, u32 addr) {
    asm volatile("ldmatrix.sync.aligned.m8n8.x4.shared.b16 {%0,%1,%2,%3}, [%4];"
                 : "=r"(r0), "=r"(r1), "=r"(r2), "=r"(r3) : "r"(addr));
}
__device__ __forceinline__ void mma16816(float* c, u32 a0, u32 a1, u32 a2, u32 a3,
                                         u32 b0, u32 b1) {
    asm volatile("mma.sync.aligned.m16n8k16.row.col.f32.bf16.bf16.f32 "
                 "{%0,%1,%2,%3}, {%4,%5,%6,%7}, {%8,%9}, {%0,%1,%2,%3};"
                 : "+f"(c[0]), "+f"(c[1]), "+f"(c[2]), "+f"(c[3])
                 : "r"(a0), "r"(a1), "r"(a2), "r"(a3), "r"(b0), "r"(b1));
}
__device__ __forceinline__ u32 ldm_addr(u32 base, int lane, int row0, int col0) {
    int r = row0 + (lane & 7) + ((lane >> 3) & 1) * 8;
    int c = col0 + (lane >> 4) * 8;
    return base + (u32)(r * PS + c) * 2u;
}
// One k16 step of split-bf16: acc += Ah*Bh + Ah*Bl + Al*Bh
template <int IM>
__device__ __forceinline__ void mma_step(float (*acc)[4][4],
                                         u32 baAh, u32 baAl, u32 baBh, u32 baBl,
                                         int lane, int mBase, int nBase, int kk) {
    u32 A[IM][4], B[4][2], C[4][2];
    u32 x0, x1, x2, x3;
#pragma unroll
    for (int im = 0; im < IM; im++)
        ldm4(A[im][0], A[im][1], A[im][2], A[im][3],
             ldm_addr(baAh, lane, mBase + im * 16, kk));
    ldm4(x0, x1, x2, x3, ldm_addr(baBh, lane, nBase, kk));
    B[0][0] = x0; B[0][1] = x2; B[1][0] = x1; B[1][1] = x3;
    ldm4(x0, x1, x2, x3, ldm_addr(baBh, lane, nBase + 16, kk));
    B[2][0] = x0; B[2][1] = x2; B[3][0] = x1; B[3][1] = x3;
#pragma unroll
    for (int im = 0; im < IM; im++)
#pragma unroll
        for (int jn = 0; jn < 4; jn++)
            mma16816(acc[im][jn], A[im][0], A[im][1], A[im][2], A[im][3], B[jn][0], B[jn][1]);
    ldm4(x0, x1, x2, x3, ldm_addr(baBl, lane, nBase, kk));
    C[0][0] = x0; C[0][1] = x2; C[1][0] = x1; C[1][1] = x3;
    ldm4(x0, x1, x2, x3, ldm_addr(baBl, lane, nBase + 16, kk));
    C[2][0] = x0; C[2][1] = x2; C[3][0] = x1; C[3][1] = x3;
#pragma unroll
    for (int im = 0; im < IM; im++)
#pragma unroll
        for (int jn = 0; jn < 4; jn++)
            mma16816(acc[im][jn], A[im][0], A[im][1], A[im][2], A[im][3], C[jn][0], C[jn][1]);
#pragma unroll
    for (int im = 0; im < IM; im++)
        ldm4(A[im][0], A[im][1], A[im][2], A[im][3],
             ldm_addr(baAl, lane, mBase + im * 16, kk));
#pragma unroll
    for (int im = 0; im < IM; im++)
#pragma unroll
        for (int jn = 0; jn < 4; jn++)
            mma16816(acc[im][jn], A[im][0], A[im][1], A[im][2], A[im][3], B[jn][0], B[jn][1]);
}

// ---------------- projection: Y[b,o,n] = sum_c W[o,c] X[b,c,n] + bias[o] -----
// A = W planes [o][c]; B = X^T planes [b][n][c]. 64(o) x 128(n), 256 thr, kc=32.
// MODE 0: fp32 [b,o,n]. MODE 1: Q/K planes [b,h,n,d]. MODE 2: V planes [b,h,d,m].
template <int MODE>
__global__ void __launch_bounds__(256)
proj_kernel(const u16* __restrict__ XTh, const u16* __restrict__ XTl,
            const u16* __restrict__ Wh, const u16* __restrict__ Wl,
            const float* __restrict__ bias, void* __restrict__ y0, void* __restrict__ y1) {
    __shared__ u16 sWh[64][PS], sWl[64][PS], sXh[128][PS], sXl[128][PS];
    const int b = blockIdx.z, o0 = blockIdx.y * 64, n0 = blockIdx.x * 128;
    const int t = threadIdx.x, lane = t & 31, w = t >> 5;
    const int wm = w & 1, wn = w >> 1;   // warp tile 32(o) x 32(n)
    const u16* Xh = XTh + (size_t)b * NN * DD;
    const u16* Xl = XTl + (size_t)b * NN * DD;
    const int ar = t >> 2, as = (t & 3) * 8;

    const u32 baWh = (u32)__cvta_generic_to_shared(&sWh[0][0]);
    const u32 baWl = (u32)__cvta_generic_to_shared(&sWl[0][0]);
    const u32 baXh = (u32)__cvta_generic_to_shared(&sXh[0][0]);
    const u32 baXl = (u32)__cvta_generic_to_shared(&sXl[0][0]);

    uint4 pa0, pa1, pbh[2], pbl[2];
    float acc[2][4][4];
#pragma unroll
    for (int i = 0; i < 2; i++)
#pragma unroll
        for (int j = 0; j < 4; j++)
#pragma unroll
            for (int k = 0; k < 4; k++) acc[i][j][k] = 0.f;

    auto load_regs = [&](int c0) {
        pa0    = *(const uint4*)&Wh[(size_t)(o0 + ar) * DD + c0 + as];
        pa1    = *(const uint4*)&Wl[(size_t)(o0 + ar) * DD + c0 + as];
        pbh[0] = *(const uint4*)&Xh[(size_t)(n0 + ar) * DD + c0 + as];
        pbl[0] = *(const uint4*)&Xl[(size_t)(n0 + ar) * DD + c0 + as];
        pbh[1] = *(const uint4*)&Xh[(size_t)(n0 + ar + 64) * DD + c0 + as];
        pbl[1] = *(const uint4*)&Xl[(size_t)(n0 + ar + 64) * DD + c0 + as];
    };
    auto store_smem = [&]() {
        *(uint4*)&sWh[ar][as]      = pa0;
        *(uint4*)&sWl[ar][as]      = pa1;
        *(uint4*)&sXh[ar][as]      = pbh[0];
        *(uint4*)&sXl[ar][as]      = pbl[0];
        *(uint4*)&sXh[ar + 64][as] = pbh[1];
        *(uint4*)&sXl[ar + 64][as] = pbl[1];
    };

    load_regs(0); store_smem(); __syncthreads();
    const int NC = DD / 32;
    for (int c = 0; c < NC; c++) {
        if (c + 1 < NC) load_regs((c + 1) * 32);
        mma_step<2>(acc, baWh, baWl, baXh, baXl, lane, wm * 32, wn * 32, 0);
        mma_step<2>(acc, baWh, baWl, baXh, baXl, lane, wm * 32, wn * 32, 16);
        if (c + 1 < NC) { __syncthreads(); store_smem(); __syncthreads(); }
    }

#pragma unroll
    for (int im = 0; im < 2; im++) {
        const int ob = o0 + wm * 32 + im * 16 + (lane >> 2);
        const float bs0 = bias[ob], bs1 = bias[ob + 8];
#pragma unroll
        for (int jn = 0; jn < 4; jn++) {
            float* cc = acc[im][jn];
            const int n = n0 + wn * 32 + jn * 8 + 2 * (lane & 3);
            const float v0 = cc[0] + bs0, v1 = cc[1] + bs0;
            const float v2 = cc[2] + bs1, v3 = cc[3] + bs1;
            if (MODE == 0) {
                float* Y = (float*)y0;
                *(float2*)&Y[((size_t)b * DD + ob) * NN + n]     = make_float2(v0, v1);
                *(float2*)&Y[((size_t)b * DD + ob + 8) * NN + n] = make_float2(v2, v3);
            } else if (MODE == 1) {
                // [b,h,n,d]: ob -> (h,d), ob+8 -> (h,d+1); d even.
                u32* Yh = (u32*)y0;
                u32* Yl = (u32*)y1;
                const int h = ob & 7, d = ob >> 3;
                size_t i0 = (((size_t)(b * HH + h) * NN + n) * DH + d) >> 1;
                Yh[i0]      = (u32)b16hi(v0) | ((u32)b16hi(v2) << 16);
                Yl[i0]      = (u32)b16lo(v0) | ((u32)b16lo(v2) << 16);
                Yh[i0 + 32] = (u32)b16hi(v1) | ((u32)b16hi(v3) << 16);
                Yl[i0 + 32] = (u32)b16lo(v1) | ((u32)b16lo(v3) << 16);
            } else {
                // [b,h,d,m]: rows d and d+1, m = n (even).
                u32* Yh = (u32*)y0;
                u32* Yl = (u32*)y1;
                const int h = ob & 7, d = ob >> 3;
                size_t i0 = (((size_t)(b * HH + h) * DH + d) * NN + n) >> 1;
                Yh[i0] = (u32)b16hi(v0) | ((u32)b16hi(v1) << 16);
                Yl[i0] = (u32)b16lo(v0) | ((u32)b16lo(v1) << 16);
                size_t i1 = i0 + (NN >> 1);
                Yh[i1] = (u32)b16hi(v2) | ((u32)b16hi(v3) << 16);
                Yl[i1] = (u32)b16lo(v2) | ((u32)b16lo(v3) << 16);
            }
        }
    }
}

// ---------------- scores: S[bh,n,m] = (1/8) sum_d Q[n,d] K[m,d] --------------
// 128x128 block, 512 threads, warp tile 32x32, kc=32 (2 chunks).
__global__ void __launch_bounds__(512)
scores_kernel() {
    __shared__ u16 sQh[128][PS], sQl[128][PS], sKh[128][PS], sKl[128][PS];
    __shared__ float sred[16];
    const int bh = blockIdx.z, n0 = blockIdx.y * 128, m0 = blockIdx.x * 128;
    const int t = threadIdx.x, lane = t & 31, w = t >> 5;
    const int wm = w & 3, wn = w >> 2;   // warp tile 32(n) x 32(m)
    const u16* Qh = g_qh + (size_t)bh * NN * DH;
    const u16* Ql = g_ql + (size_t)bh * NN * DH;
    const u16* Kh = g_kh + (size_t)bh * NN * DH;
    const u16* Kl = g_kl + (size_t)bh * NN * DH;

    const u32 baQh = (u32)__cvta_generic_to_shared(&sQh[0][0]);
    const u32 baQl = (u32)__cvta_generic_to_shared(&sQl[0][0]);
    const u32 baKh = (u32)__cvta_generic_to_shared(&sKh[0][0]);
    const u32 baKl = (u32)__cvta_generic_to_shared(&sKl[0][0]);

    float acc[2][4][4];
#pragma unroll
    for (int i = 0; i < 2; i++)
#pragma unroll
        for (int j = 0; j < 4; j++)
#pragma unroll
            for (int k = 0; k < 4; k++) acc[i][j][k] = 0.f;

    const int r = t >> 2, s = (t & 3) * 8;   // 512 threads -> 1 uint4/plane
    for (int cc = 0; cc < 2; cc++) {
        const int c0 = cc * 32;
        if (cc) __syncthreads();
        *(uint4*)&sQh[r][s] = *(const uint4*)&Qh[(size_t)(n0 + r) * DH + c0 + s];
        *(uint4*)&sQl[r][s] = *(const uint4*)&Ql[(size_t)(n0 + r) * DH + c0 + s];
        *(uint4*)&sKh[r][s] = *(const uint4*)&Kh[(size_t)(m0 + r) * DH + c0 + s];
        *(uint4*)&sKl[r][s] = *(const uint4*)&Kl[(size_t)(m0 + r) * DH + c0 + s];
        __syncthreads();
        mma_step<2>(acc, baQh, baQl, baKh, baKl, lane, wm * 32, wn * 32, 0);
        mma_step<2>(acc, baQh, baQl, baKh, baKl, lane, wm * 32, wn * 32, 16);
    }

    float mn = __int_as_float(0x7f800000);
#pragma unroll
    for (int im = 0; im < 2; im++) {
        const int n = n0 + wm * 32 + im * 16 + (lane >> 2);
#pragma unroll
        for (int jn = 0; jn < 4; jn++) {
            float* cc = acc[im][jn];
            const int m = m0 + wn * 32 + jn * 8 + 2 * (lane & 3);
            float2 r0 = make_float2(cc[0] * 0.125f, cc[1] * 0.125f);
            float2 r1 = make_float2(cc[2] * 0.125f, cc[3] * 0.125f);
            mn = fminf(mn, fminf(fminf(r0.x, r0.y), fminf(r1.x, r1.y)));
            *(float2*)&g_s[((size_t)bh * NN + n) * NN + m]     = r0;
            *(float2*)&g_s[((size_t)bh * NN + n + 8) * NN + m] = r1;
        }
    }
#pragma unroll
    for (int o = 16; o > 0; o >>= 1) mn = fminf(mn, __shfl_xor_sync(0xffffffffu, mn, o));
    if (lane == 0) sred[w] = mn;
    __syncthreads();
    if (t == 0) {
        float v = sred[0];
#pragma unroll
        for (int i = 1; i < 16; i++) v = fminf(v, sred[i]);
        atomicMin(&g_minenc, enc_f(v));
    }
}

// ---------------- output 2 ---------------------------------------------------
__global__ void __launch_bounds__(256)
out2_kernel(float* __restrict__ O2) {
    const int idx = blockIdx.x * 256 + threadIdx.x;
    const int total = BB * NN * NN / 4;
    if (idx >= total) return;
    const int e = idx * 4;
    const int m = e % NN;
    const int n = (e / NN) % NN;
    const int b = e / (NN * NN);

    float4 acc = make_float4(0.f, 0.f, 0.f, 0.f);
#pragma unroll
    for (int h = 0; h < HH; h++) {
        float4 s = *(const float4*)&g_s[((size_t)(b * HH + h) * NN + n) * NN + m];
        acc.x += s.x; acc.y += s.y; acc.z += s.z; acc.w += s.w;
    }
    const float pen = dec_f(g_minenc) - 20.0f;
    uchar4 mk = *(const uchar4*)&g_mask[(size_t)n * NN + m];
    acc.x = acc.x * 0.125f + (mk.x ? 0.f : pen);
    acc.y = acc.y * 0.125f + (mk.y ? 0.f : pen);
    acc.z = acc.z * 0.125f + (mk.z ? 0.f : pen);
    acc.w = acc.w * 0.125f + (mk.w ? 0.f : pen);
    *(float4*)&O2[e] = acc;
}

// ---------------- softmax: in-place split of each row into hi|lo planes ------
__global__ void __launch_bounds__(256)
softmax_kernel() {
    const int row = blockIdx.x;          // bh*NN + n
    const int n   = row % NN;
    float* S = g_s + (size_t)row * NN;
    u16* Sh = (u16*)S;                   // halves [0..NN) = hi, [NN..2NN) = lo
    const unsigned char* mrow = g_mask + (size_t)n * NN;
    const int tid = threadIdx.x;
    const float pen = dec_f(g_minenc) - 20.0f;

    __shared__ float sredA[8];
    __shared__ float sredB[8];

    float v[6];
    float mx = __int_as_float(0xff800000);
#pragma unroll
    for (int i = 0; i < 6; i++) {
        int m = tid + i * 256;
        float s = S[m];
        if (!mrow[m]) s += pen;
        v[i] = s;
        mx = fmaxf(mx, s);
    }
#pragma unroll
    for (int o = 16; o > 0; o >>= 1) mx = fmaxf(mx, __shfl_xor_sync(0xffffffffu, mx, o));
    if ((tid & 31) == 0) sredA[tid >> 5] = mx;
    __syncthreads();
    mx = sredA[0];
#pragma unroll
    for (int i = 1; i < 8; i++) mx = fmaxf(mx, sredA[i]);

    float sum = 0.f;
#pragma unroll
    for (int i = 0; i < 6; i++) {
        v[i] = __expf(v[i] - mx);
        sum += v[i];
    }
#pragma unroll
    for (int o = 16; o > 0; o >>= 1) sum += __shfl_xor_sync(0xffffffffu, sum, o);
    if ((tid & 31) == 0) sredB[tid >> 5] = sum;
    __syncthreads();
    sum = sredB[0];
#pragma unroll
    for (int i = 1; i < 8; i++) sum += sredB[i];
    const float inv = 1.0f / sum;
    __syncthreads();   // all fp32 reads complete before 16-bit overwrite
#pragma unroll
    for (int i = 0; i < 6; i++) {
        int m = tid + i * 256;
        float p = v[i] * inv;
        __nv_bfloat16 hb = __float2bfloat16(p);
        Sh[m]      = __bfloat16_as_ushort(hb);
        Sh[NN + m] = __bfloat16_as_ushort(__float2bfloat16(p - __bfloat162float(hb)));
    }
}

// ---------------- PV: x[n,d] = sum_m P[n,m] V[d,m] -> split planes [b,n,c] ---
// 128(n) x 64(d) block, 256 thr, warp tile 32x32, kc=32 over m (48 chunks).
__global__ void __launch_bounds__(256)
pv_kernel() {
    __shared__ u16 sPh[128][PS], sPl[128][PS], sVh[64][PS], sVl[64][PS];
    const int bh = blockIdx.y, n0 = blockIdx.x * 128;
    const int t = threadIdx.x, lane = t & 31, w = t >> 5;
    const int wm = w >> 1, wn = w & 1;   // warp tile 32(n) x 32(d)
    const u16* srow = (const u16*)g_s;   // row n: 2*NN halves; hi [0,NN), lo [NN,2NN)
    const u16* Vh = g_vh + (size_t)bh * DH * NN;
    const u16* Vl = g_vl + (size_t)bh * DH * NN;

    const u32 baPh = (u32)__cvta_generic_to_shared(&sPh[0][0]);
    const u32 baPl = (u32)__cvta_generic_to_shared(&sPl[0][0]);
    const u32 baVh = (u32)__cvta_generic_to_shared(&sVh[0][0]);
    const u32 baVl = (u32)__cvta_generic_to_shared(&sVl[0][0]);

    const int pr = t >> 2, psv = (t & 3) * 8;    // P: rows pr & pr+64; V: row pr (0..63)
    uint4 pph[2], ppl[2], pvh, pvl;
    float acc[2][4][4];
#pragma unroll
    for (int i = 0; i < 2; i++)
#pragma unroll
        for (int j = 0; j < 4; j++)
#pragma unroll
            for (int k = 0; k < 4; k++) acc[i][j][k] = 0.f;

    auto load_regs = [&](int m0c) {
        size_t rb0 = (size_t)(bh * NN + n0 + pr) * (2 * NN);
        size_t rb1 = (size_t)(bh * NN + n0 + pr + 64) * (2 * NN);
        pph[0] = *(const uint4*)&srow[rb0 + m0c + psv];
        ppl[0] = *(const uint4*)&srow[rb0 + NN + m0c + psv];
        pph[1] = *(const uint4*)&srow[rb1 + m0c + psv];
        ppl[1] = *(const uint4*)&srow[rb1 + NN + m0c + psv];
        pvh = *(const uint4*)&Vh[(size_t)pr * NN + m0c + psv];
        pvl = *(const uint4*)&Vl[(size_t)pr * NN + m0c + psv];
    };
    auto store_smem = [&]() {
        *(uint4*)&sPh[pr][psv]      = pph[0];
        *(uint4*)&sPl[pr][psv]      = ppl[0];
        *(uint4*)&sPh[pr + 64][psv] = pph[1];
        *(uint4*)&sPl[pr + 64][psv] = ppl[1];
        *(uint4*)&sVh[pr][psv]      = pvh;
        *(uint4*)&sVl[pr][psv]      = pvl;
    };

    load_regs(0); store_smem(); __syncthreads();
    const int NC = NN / 32;
    for (int c = 0; c < NC; c++) {
        if (c + 1 < NC) load_regs((c + 1) * 32);
        mma_step<2>(acc, baPh, baPl, baVh, baVl, lane, wm * 32, wn * 32, 0);
        mma_step<2>(acc, baPh, baPl, baVh, baVl, lane, wm * 32, wn * 32, 16);
        if (c + 1 < NC) { __syncthreads(); store_smem(); __syncthreads(); }
    }

    const int b = bh >> 3, h = bh & 7;
#pragma unroll
    for (int im = 0; im < 2; im++) {
        const int n = n0 + wm * 32 + im * 16 + (lane >> 2);
#pragma unroll
        for (int jn = 0; jn < 4; jn++) {
            float* cc = acc[im][jn];
            const int d  = wn * 32 + jn * 8 + 2 * (lane & 3);
            const int c0i = d * 8 + h, c1i = (d + 1) * 8 + h;
            size_t base0 = ((size_t)b * NN + n) * DD;
            size_t base1 = base0 + (size_t)8 * DD;   // n + 8
            g_xth[base0 + c0i] = b16hi(cc[0]);  g_xtl[base0 + c0i] = b16lo(cc[0]);
            g_xth[base0 + c1i] = b16hi(cc[1]);  g_xtl[base0 + c1i] = b16lo(cc[1]);
            g_xth[base1 + c0i] = b16hi(cc[2]);  g_xtl[base1 + c0i] = b16lo(cc[2]);
            g_xth[base1 + c1i] = b16hi(cc[3]);  g_xtl[base1 + c1i] = b16lo(cc[3]);
        }
    }
}

// ---------------- launch ------------------------------------------------------
extern "C" void kernel_launch(void* const* d_in, const int* in_sizes, int n_in,
                              void* d_out, int out_size) {
    const float* query = (const float*)d_in[0];
    const float* key   = (const float*)d_in[1];
    const float* value = (const float*)d_in[2];
    // d_in[3] = dist (unused)
    const void* mask   = d_in[4];
    const float* Wq = (const float*)d_in[5];
    const float* bq = (const float*)d_in[6];
    const float* Wk = (const float*)d_in[7];
    const float* bk = (const float*)d_in[8];
    const float* Wv = (const float*)d_in[9];
    const float* bv = (const float*)d_in[10];
    const float* Wm = (const float*)d_in[11];
    const float* bm = (const float*)d_in[12];

    float* out  = (float*)d_out;                 // [B, D, N]
    float* out2 = out + (size_t)BB * DD * NN;    // [B, N, N]

    void *pih, *pil, *pwh, *pwl, *pqh, *pql, *pkh, *pkl, *pvh, *pvl, *pxth, *pxtl;
    cudaGetSymbolAddress(&pih, g_ith);
    cudaGetSymbolAddress(&pil, g_itl);
    cudaGetSymbolAddress(&pwh, g_wh);
    cudaGetSymbolAddress(&pwl, g_wl);
    cudaGetSymbolAddress(&pqh, g_qh);
    cudaGetSymbolAddress(&pql, g_ql);
    cudaGetSymbolAddress(&pkh, g_kh);
    cudaGetSymbolAddress(&pkl, g_kl);
    cudaGetSymbolAddress(&pvh, g_vh);
    cudaGetSymbolAddress(&pvl, g_vl);
    cudaGetSymbolAddress(&pxth, g_xth);
    cudaGetSymbolAddress(&pxtl, g_xtl);

    const u16* ith = (const u16*)pih;
    const u16* itl = (const u16*)pil;
    const u16* wh  = (const u16*)pwh;
    const u16* wl  = (const u16*)pwl;
    const size_t IB = (size_t)BB * NN * DD;   // per-input plane stride
    const size_t WB = (size_t)DD * DD;        // per-weight plane stride

    init_kernel<<<1, 1>>>();
    mask_classify_kernel<<<256, 256>>>((const u32*)mask);
    mask_convert_kernel<<<256, 256>>>(mask);

    presplit_in_kernel<<<dim3(NN / 32, DD / 32, 3 * BB), dim3(32, 8)>>>(query, key, value);
    presplit_w_kernel<<<1024, 256>>>(Wq, Wk, Wv, Wm);

    dim3 gproj(NN / 128, DD / 64, BB);
    proj_kernel<1><<<gproj, 256>>>(ith + 0 * IB, itl + 0 * IB, wh + 0 * WB, wl + 0 * WB, bq, pqh, pql);
    proj_kernel<1><<<gproj, 256>>>(ith + 1 * IB, itl + 1 * IB, wh + 1 * WB, wl + 1 * WB, bk, pkh, pkl);
    proj_kernel<2><<<gproj, 256>>>(ith + 2 * IB, itl + 2 * IB, wh + 2 * WB, wl + 2 * WB, bv, pvh, pvl);

    scores_kernel<<<dim3(NN / 128, NN / 128, BB * HH), 512>>>();

    {
        int total4 = BB * NN * NN / 4;
        out2_kernel<<<(total4 + 255) / 256, 256>>>(out2);
    }

    softmax_kernel<<<BB * HH * NN, 256>>>();

    pv_kernel<<<dim3(NN / 128, BB * HH), 256>>>();

    proj_kernel<0><<<gproj, 256>>>((const u16*)pxth, (const u16*)pxtl,
                                   wh + 3 * WB, wl + 3 * WB, bm, out, nullptr);
}

// round 8
// speedup vs baseline: 1.7296x; 1.1699x over previous
#include <cuda_runtime.h>
#include <cuda_bf16.h>
#include <cstdint>

#define BB 4
#define DD 512
#define NN 1536
#define HH 8
#define DH 64
#define PS 40   // smem row stride in halves (32 k + 8 pad -> conflict-free ldmatrix)

typedef unsigned short u16;
typedef unsigned int   u32;

// ---------------- scratch (device globals) -----------------------------------
__device__ __align__(16) u16 g_ith[(size_t)3 * BB * NN * DD];  // inputs^T hi [which][b][n][c]
__device__ __align__(16) u16 g_itl[(size_t)3 * BB * NN * DD];  // inputs^T lo
__device__ __align__(16) u16 g_wh[(size_t)4 * DD * DD];        // weights hi [which][o][c]
__device__ __align__(16) u16 g_wl[(size_t)4 * DD * DD];
__device__ __align__(16) u16 g_qh[(size_t)BB * HH * NN * DH];  // [b,h,n,d]
__device__ __align__(16) u16 g_ql[(size_t)BB * HH * NN * DH];
__device__ __align__(16) u16 g_kh[(size_t)BB * HH * NN * DH];  // [b,h,m,d]
__device__ __align__(16) u16 g_kl[(size_t)BB * HH * NN * DH];
__device__ __align__(16) u16 g_vh[(size_t)BB * HH * DH * NN];  // [b,h,d,m]
__device__ __align__(16) u16 g_vl[(size_t)BB * HH * DH * NN];
__device__ float g_s[(size_t)BB * HH * NN * NN];   // fp32 scores -> in-place split planes
__device__ __align__(16) u16 g_xth[(size_t)BB * NN * DD];      // PV out^T hi [b][n][c]
__device__ __align__(16) u16 g_xtl[(size_t)BB * NN * DD];
__device__ unsigned char g_mask[(size_t)NN * NN];
__device__ u32 g_minenc;
__device__ u32 g_maskflags;

// ---------------- helpers ----------------------------------------------------
__device__ __forceinline__ u32 enc_f(float x) {
    u32 b = __float_as_uint(x);
    return (b & 0x80000000u) ? ~b : (b | 0x80000000u);
}
__device__ __forceinline__ float dec_f(u32 e) {
    return (e & 0x80000000u) ? __uint_as_float(e ^ 0x80000000u)
                             : __uint_as_float(~e);
}
__device__ __forceinline__ u16 b16hi(float x) {
    return __bfloat16_as_ushort(__float2bfloat16(x));
}
__device__ __forceinline__ u16 b16lo(float x) {
    float hf = __bfloat162float(__float2bfloat16(x));
    return __bfloat16_as_ushort(__float2bfloat16(x - hf));
}
__device__ __forceinline__ void cp16(u32 dst, const void* src) {
    asm volatile("cp.async.ca.shared.global [%0], [%1], 16;" :: "r"(dst), "l"(src));
}
#define CP_COMMIT() asm volatile("cp.async.commit_group;" ::: "memory")
#define CP_WAIT0()  asm volatile("cp.async.wait_group 0;" ::: "memory")

__global__ void init_kernel() { g_minenc = 0xFFFFFFFFu; g_maskflags = 0u; }

// ---------------- mask dtype classification + normalization ------------------
__global__ void __launch_bounds__(256)
mask_classify_kernel(const u32* __restrict__ mw) {
    const int total = NN * NN / 4;
    u32 local = 0;
    for (int i = blockIdx.x * 256 + threadIdx.x; i < total; i += gridDim.x * 256) {
        u32 w = mw[i];
        if (w != 0u && w != 1u)          local |= 1u;
        if (w != 0u && w != 0x3f800000u) local |= 2u;
    }
#pragma unroll
    for (int o = 16; o > 0; o >>= 1) local |= __shfl_xor_sync(0xffffffffu, local, o);
    if ((threadIdx.x & 31) == 0 && local) atomicOr(&g_maskflags, local);
}

__global__ void __launch_bounds__(256)
mask_convert_kernel(const void* __restrict__ mraw) {
    const u32 f = g_maskflags;
    const int mode = ((f & 2u) == 0u) ? 2 : (((f & 1u) == 0u) ? 1 : 0);
    const int total = NN * NN;
    if (mode == 0) {
        const unsigned char* m8 = (const unsigned char*)mraw;
        for (int i = blockIdx.x * 256 + threadIdx.x; i < total; i += gridDim.x * 256)
            g_mask[i] = m8[i] ? 1 : 0;
    } else if (mode == 1) {
        const int* mi = (const int*)mraw;
        for (int i = blockIdx.x * 256 + threadIdx.x; i < total; i += gridDim.x * 256)
            g_mask[i] = mi[i] ? 1 : 0;
    } else {
        const float* mf = (const float*)mraw;
        for (int i = blockIdx.x * 256 + threadIdx.x; i < total; i += gridDim.x * 256)
            g_mask[i] = (mf[i] != 0.0f) ? 1 : 0;
    }
}

// ---------------- prepasses: split inputs/weights into bf16 planes -----------
__global__ void __launch_bounds__(256)
presplit_in_kernel(const float* __restrict__ q, const float* __restrict__ k,
                   const float* __restrict__ v) {
    __shared__ float tile[32][33];
    const int which = blockIdx.z >> 2, b = blockIdx.z & 3;
    const float* src = (which == 0 ? q : which == 1 ? k : v) + (size_t)b * DD * NN;
    const int n0 = blockIdx.x * 32, c0 = blockIdx.y * 32;
    const int tx = threadIdx.x, ty = threadIdx.y;  // 32 x 8
#pragma unroll
    for (int i = 0; i < 32; i += 8)
        tile[ty + i][tx] = src[(size_t)(c0 + ty + i) * NN + n0 + tx];
    __syncthreads();
    u16* dh = g_ith + (size_t)(which * BB + b) * NN * DD;
    u16* dl = g_itl + (size_t)(which * BB + b) * NN * DD;
#pragma unroll
    for (int i = 0; i < 32; i += 8) {
        float x = tile[tx][ty + i];
        size_t o = (size_t)(n0 + ty + i) * DD + c0 + tx;
        dh[o] = b16hi(x);
        dl[o] = b16lo(x);
    }
}

__global__ void __launch_bounds__(256)
presplit_w_kernel(const float* __restrict__ Wq, const float* __restrict__ Wk,
                  const float* __restrict__ Wv, const float* __restrict__ Wm) {
    const int total = 4 * DD * DD;
    for (int i = blockIdx.x * 256 + threadIdx.x; i < total; i += gridDim.x * 256) {
        int w = i >> 18;
        int r = i & (DD * DD - 1);
        const float* src = (w == 0 ? Wq : w == 1 ? Wk : w == 2 ? Wv : Wm);
        float x = src[r];
        g_wh[i] = b16hi(x);
        g_wl[i] = b16lo(x);
    }
}

// ---------------- mma.sync machinery -----------------------------------------
__device__ __forceinline__ void ldm4(u32& r0, u32& r1, u32& r2, u32& r3, u32 addr) {
    asm volatile("ldmatrix.sync.aligned.m8n8.x4.shared.b16 {%0,%1,%2,%3}, [%4];"
                 : "=r"(r0), "=r"(r1), "=r"(r2), "=r"(r3) : "r"(addr));
}
__device__ __forceinline__ void mma16816(float* c, u32 a0, u32 a1, u32 a2, u32 a3,
                                         u32 b0, u32 b1) {
    asm volatile("mma.sync.aligned.m16n8k16.row.col.f32.bf16.bf16.f32 "
                 "{%0,%1,%2,%3}, {%4,%5,%6,%7}, {%8,%9}, {%0,%1,%2,%3};"
                 : "+f"(c[0]), "+f"(c[1]), "+f"(c[2]), "+f"(c[3])
                 : "r"(a0), "r"(a1), "r"(a2), "r"(a3), "r"(b0), "r"(b1));
}
template <int SPS>
__device__ __forceinline__ u32 ldm_addr(u32 base, int lane, int row0, int col0) {
    int r = row0 + (lane & 7) + ((lane >> 3) & 1) * 8;
    int c = col0 + (lane >> 4) * 8;
    return base + (u32)(r * SPS + c) * 2u;
}
// One k16 step of split-bf16: acc += Ah*Bh + Ah*Bl + Al*Bh
template <int IM, int SPS>
__device__ __forceinline__ void mma_step(float (*acc)[4][4],
                                         u32 baAh, u32 baAl, u32 baBh, u32 baBl,
                                         int lane, int mBase, int nBase, int kk) {
    u32 A[IM][4], B[4][2], C[4][2];
    u32 x0, x1, x2, x3;
#pragma unroll
    for (int im = 0; im < IM; im++)
        ldm4(A[im][0], A[im][1], A[im][2], A[im][3],
             ldm_addr<SPS>(baAh, lane, mBase + im * 16, kk));
    ldm4(x0, x1, x2, x3, ldm_addr<SPS>(baBh, lane, nBase, kk));
    B[0][0] = x0; B[0][1] = x2; B[1][0] = x1; B[1][1] = x3;
    ldm4(x0, x1, x2, x3, ldm_addr<SPS>(baBh, lane, nBase + 16, kk));
    B[2][0] = x0; B[2][1] = x2; B[3][0] = x1; B[3][1] = x3;
#pragma unroll
    for (int im = 0; im < IM; im++)
#pragma unroll
        for (int jn = 0; jn < 4; jn++)
            mma16816(acc[im][jn], A[im][0], A[im][1], A[im][2], A[im][3], B[jn][0], B[jn][1]);
    ldm4(x0, x1, x2, x3, ldm_addr<SPS>(baBl, lane, nBase, kk));
    C[0][0] = x0; C[0][1] = x2; C[1][0] = x1; C[1][1] = x3;
    ldm4(x0, x1, x2, x3, ldm_addr<SPS>(baBl, lane, nBase + 16, kk));
    C[2][0] = x0; C[2][1] = x2; C[3][0] = x1; C[3][1] = x3;
#pragma unroll
    for (int im = 0; im < IM; im++)
#pragma unroll
        for (int jn = 0; jn < 4; jn++)
            mma16816(acc[im][jn], A[im][0], A[im][1], A[im][2], A[im][3], C[jn][0], C[jn][1]);
#pragma unroll
    for (int im = 0; im < IM; im++)
        ldm4(A[im][0], A[im][1], A[im][2], A[im][3],
             ldm_addr<SPS>(baAl, lane, mBase + im * 16, kk));
#pragma unroll
    for (int im = 0; im < IM; im++)
#pragma unroll
        for (int jn = 0; jn < 4; jn++)
            mma16816(acc[im][jn], A[im][0], A[im][1], A[im][2], A[im][3], B[jn][0], B[jn][1]);
}

// ---------------- projection: Y[b,o,n] = sum_c W[o,c] X[b,c,n] + bias[o] -----
template <int MODE>
__global__ void __launch_bounds__(256)
proj_kernel(const u16* __restrict__ XTh, const u16* __restrict__ XTl,
            const u16* __restrict__ Wh, const u16* __restrict__ Wl,
            const float* __restrict__ bias, void* __restrict__ y0, void* __restrict__ y1) {
    __shared__ u16 sWh[64][PS], sWl[64][PS], sXh[128][PS], sXl[128][PS];
    const int b = blockIdx.z, o0 = blockIdx.y * 64, n0 = blockIdx.x * 128;
    const int t = threadIdx.x, lane = t & 31, w = t >> 5;
    const int wm = w & 1, wn = w >> 1;
    const u16* Xh = XTh + (size_t)b * NN * DD;
    const u16* Xl = XTl + (size_t)b * NN * DD;
    const int ar = t >> 2, as = (t & 3) * 8;

    const u32 baWh = (u32)__cvta_generic_to_shared(&sWh[0][0]);
    const u32 baWl = (u32)__cvta_generic_to_shared(&sWl[0][0]);
    const u32 baXh = (u32)__cvta_generic_to_shared(&sXh[0][0]);
    const u32 baXl = (u32)__cvta_generic_to_shared(&sXl[0][0]);

    uint4 pa0, pa1, pbh[2], pbl[2];
    float acc[2][4][4];
#pragma unroll
    for (int i = 0; i < 2; i++)
#pragma unroll
        for (int j = 0; j < 4; j++)
#pragma unroll
            for (int k = 0; k < 4; k++) acc[i][j][k] = 0.f;

    auto load_regs = [&](int c0) {
        pa0    = *(const uint4*)&Wh[(size_t)(o0 + ar) * DD + c0 + as];
        pa1    = *(const uint4*)&Wl[(size_t)(o0 + ar) * DD + c0 + as];
        pbh[0] = *(const uint4*)&Xh[(size_t)(n0 + ar) * DD + c0 + as];
        pbl[0] = *(const uint4*)&Xl[(size_t)(n0 + ar) * DD + c0 + as];
        pbh[1] = *(const uint4*)&Xh[(size_t)(n0 + ar + 64) * DD + c0 + as];
        pbl[1] = *(const uint4*)&Xl[(size_t)(n0 + ar + 64) * DD + c0 + as];
    };
    auto store_smem = [&]() {
        *(uint4*)&sWh[ar][as]      = pa0;
        *(uint4*)&sWl[ar][as]      = pa1;
        *(uint4*)&sXh[ar][as]      = pbh[0];
        *(uint4*)&sXl[ar][as]      = pbl[0];
        *(uint4*)&sXh[ar + 64][as] = pbh[1];
        *(uint4*)&sXl[ar + 64][as] = pbl[1];
    };

    load_regs(0); store_smem(); __syncthreads();
    const int NC = DD / 32;
    for (int c = 0; c < NC; c++) {
        if (c + 1 < NC) load_regs((c + 1) * 32);
        mma_step<2, PS>(acc, baWh, baWl, baXh, baXl, lane, wm * 32, wn * 32, 0);
        mma_step<2, PS>(acc, baWh, baWl, baXh, baXl, lane, wm * 32, wn * 32, 16);
        if (c + 1 < NC) { __syncthreads(); store_smem(); __syncthreads(); }
    }

#pragma unroll
    for (int im = 0; im < 2; im++) {
        const int ob = o0 + wm * 32 + im * 16 + (lane >> 2);
        const float bs0 = bias[ob], bs1 = bias[ob + 8];
#pragma unroll
        for (int jn = 0; jn < 4; jn++) {
            float* cc = acc[im][jn];
            const int n = n0 + wn * 32 + jn * 8 + 2 * (lane & 3);
            const float v0 = cc[0] + bs0, v1 = cc[1] + bs0;
            const float v2 = cc[2] + bs1, v3 = cc[3] + bs1;
            if (MODE == 0) {
                float* Y = (float*)y0;
                *(float2*)&Y[((size_t)b * DD + ob) * NN + n]     = make_float2(v0, v1);
                *(float2*)&Y[((size_t)b * DD + ob + 8) * NN + n] = make_float2(v2, v3);
            } else if (MODE == 1) {
                u32* Yh = (u32*)y0;
                u32* Yl = (u32*)y1;
                const int h = ob & 7, d = ob >> 3;
                size_t i0 = (((size_t)(b * HH + h) * NN + n) * DH + d) >> 1;
                Yh[i0]      = (u32)b16hi(v0) | ((u32)b16hi(v2) << 16);
                Yl[i0]      = (u32)b16lo(v0) | ((u32)b16lo(v2) << 16);
                Yh[i0 + 32] = (u32)b16hi(v1) | ((u32)b16hi(v3) << 16);
                Yl[i0 + 32] = (u32)b16lo(v1) | ((u32)b16lo(v3) << 16);
            } else {
                u32* Yh = (u32*)y0;
                u32* Yl = (u32*)y1;
                const int h = ob & 7, d = ob >> 3;
                size_t i0 = (((size_t)(b * HH + h) * DH + d) * NN + n) >> 1;
                Yh[i0] = (u32)b16hi(v0) | ((u32)b16hi(v1) << 16);
                Yl[i0] = (u32)b16lo(v0) | ((u32)b16lo(v1) << 16);
                size_t i1 = i0 + (NN >> 1);
                Yh[i1] = (u32)b16hi(v2) | ((u32)b16hi(v3) << 16);
                Yl[i1] = (u32)b16lo(v2) | ((u32)b16lo(v3) << 16);
            }
        }
    }
}

// ---------------- scores: single k-chunk of 64, cp.async fill ----------------
// dynamic smem: 4 planes of 128 rows x 72 halves (144B rows, 16B aligned)
#define PS2 72
#define SC_PLANE (128 * PS2 * 2)              // 18432 B
#define SC_SMEM  (4 * SC_PLANE)               // 73728 B
__global__ void __launch_bounds__(512)
scores_kernel() {
    extern __shared__ __align__(16) char dsm[];
    __shared__ float sred[16];
    const int bh = blockIdx.z, n0 = blockIdx.y * 128, m0 = blockIdx.x * 128;
    const int t = threadIdx.x, lane = t & 31, w = t >> 5;
    const int wm = w & 3, wn = w >> 2;   // warp tile 32(n) x 32(m)
    const u16* Qh = g_qh + (size_t)bh * NN * DH;
    const u16* Ql = g_ql + (size_t)bh * NN * DH;
    const u16* Kh = g_kh + (size_t)bh * NN * DH;
    const u16* Kl = g_kl + (size_t)bh * NN * DH;

    const u32 sbase = (u32)__cvta_generic_to_shared(dsm);
    const u32 baQh = sbase, baQl = sbase + SC_PLANE;
    const u32 baKh = sbase + 2 * SC_PLANE, baKl = sbase + 3 * SC_PLANE;

#pragma unroll
    for (int rep = 0; rep < 2; rep++) {
        const int idx = t + rep * 512;
        const int row = idx >> 3, c8 = (idx & 7) * 8;
        const u32 off = (u32)(row * PS2 + c8) * 2u;
        cp16(baQh + off, &Qh[(size_t)(n0 + row) * DH + c8]);
        cp16(baQl + off, &Ql[(size_t)(n0 + row) * DH + c8]);
        cp16(baKh + off, &Kh[(size_t)(m0 + row) * DH + c8]);
        cp16(baKl + off, &Kl[(size_t)(m0 + row) * DH + c8]);
    }
    CP_COMMIT();
    CP_WAIT0();
    __syncthreads();

    float acc[2][4][4];
#pragma unroll
    for (int i = 0; i < 2; i++)
#pragma unroll
        for (int j = 0; j < 4; j++)
#pragma unroll
            for (int k = 0; k < 4; k++) acc[i][j][k] = 0.f;

#pragma unroll
    for (int kk = 0; kk < 64; kk += 16)
        mma_step<2, PS2>(acc, baQh, baQl, baKh, baKl, lane, wm * 32, wn * 32, kk);

    float mn = __int_as_float(0x7f800000);
#pragma unroll
    for (int im = 0; im < 2; im++) {
        const int n = n0 + wm * 32 + im * 16 + (lane >> 2);
#pragma unroll
        for (int jn = 0; jn < 4; jn++) {
            float* cc = acc[im][jn];
            const int m = m0 + wn * 32 + jn * 8 + 2 * (lane & 3);
            float2 r0 = make_float2(cc[0] * 0.125f, cc[1] * 0.125f);
            float2 r1 = make_float2(cc[2] * 0.125f, cc[3] * 0.125f);
            mn = fminf(mn, fminf(fminf(r0.x, r0.y), fminf(r1.x, r1.y)));
            *(float2*)&g_s[((size_t)bh * NN + n) * NN + m]     = r0;
            *(float2*)&g_s[((size_t)bh * NN + n + 8) * NN + m] = r1;
        }
    }
#pragma unroll
    for (int o = 16; o > 0; o >>= 1) mn = fminf(mn, __shfl_xor_sync(0xffffffffu, mn, o));
    if (lane == 0) sred[w] = mn;
    __syncthreads();
    if (t == 0) {
        float v = sred[0];
#pragma unroll
        for (int i = 1; i < 16; i++) v = fminf(v, sred[i]);
        atomicMin(&g_minenc, enc_f(v));
    }
}

// ---------------- fused out2 + softmax ---------------------------------------
// block = (n, b); loads all 8 head rows once, writes out2 row + split planes.
__global__ void __launch_bounds__(256)
osmax_kernel(float* __restrict__ O2) {
    const int n = blockIdx.x, b = blockIdx.y;
    const int tid = threadIdx.x, lane = tid & 31, wid = tid >> 5;
    const float pen = dec_f(g_minenc) - 20.0f;
    const unsigned char* mrow = g_mask + (size_t)n * NN;

    __shared__ float sred[8][9];

    bool km[6];
#pragma unroll
    for (int i = 0; i < 6; i++) km[i] = mrow[tid + i * 256] != 0;

    float v[8][6];
#pragma unroll
    for (int h = 0; h < 8; h++) {
        const float* S = g_s + ((size_t)(b * HH + h) * NN + n) * NN;
#pragma unroll
        for (int i = 0; i < 6; i++) {
            float s = S[tid + i * 256];
            if (!km[i]) s += pen;
            v[h][i] = s;
        }
    }

    // out2 row: mean over heads (pen folds in exactly; same for all h)
    {
        float* o2 = &O2[((size_t)b * NN + n) * NN];
#pragma unroll
        for (int i = 0; i < 6; i++) {
            float s = v[0][i] + v[1][i] + v[2][i] + v[3][i]
                    + v[4][i] + v[5][i] + v[6][i] + v[7][i];
            o2[tid + i * 256] = s * 0.125f;
        }
    }

    // per-head max
    float mx[8];
#pragma unroll
    for (int h = 0; h < 8; h++) {
        float m = v[h][0];
#pragma unroll
        for (int i = 1; i < 6; i++) m = fmaxf(m, v[h][i]);
#pragma unroll
        for (int o = 16; o > 0; o >>= 1) m = fmaxf(m, __shfl_xor_sync(0xffffffffu, m, o));
        mx[h] = m;
    }
    if (lane == 0)
#pragma unroll
        for (int h = 0; h < 8; h++) sred[h][wid] = mx[h];
    __syncthreads();
#pragma unroll
    for (int h = 0; h < 8; h++) {
        float m = sred[h][0];
#pragma unroll
        for (int w2 = 1; w2 < 8; w2++) m = fmaxf(m, sred[h][w2]);
        mx[h] = m;
    }
    __syncthreads();

    // exp + per-head sum
    float inv[8];
#pragma unroll
    for (int h = 0; h < 8; h++) {
        float s = 0.f;
#pragma unroll
        for (int i = 0; i < 6; i++) {
            v[h][i] = __expf(v[h][i] - mx[h]);
            s += v[h][i];
        }
#pragma unroll
        for (int o = 16; o > 0; o >>= 1) s += __shfl_xor_sync(0xffffffffu, s, o);
        inv[h] = s;
    }
    if (lane == 0)
#pragma unroll
        for (int h = 0; h < 8; h++) sred[h][wid] = inv[h];
    __syncthreads();
#pragma unroll
    for (int h = 0; h < 8; h++) {
        float s = sred[h][0];
#pragma unroll
        for (int w2 = 1; w2 < 8; w2++) s += sred[h][w2];
        inv[h] = 1.0f / s;
    }
    // all fp32 reads done (regs) + barrier passed -> safe in-place 16-bit write
#pragma unroll
    for (int h = 0; h < 8; h++) {
        u16* Sh = (u16*)(g_s + ((size_t)(b * HH + h) * NN + n) * NN);
#pragma unroll
        for (int i = 0; i < 6; i++) {
            int m = tid + i * 256;
            float p = v[h][i] * inv[h];
            __nv_bfloat16 hb = __float2bfloat16(p);
            Sh[m]      = __bfloat16_as_ushort(hb);
            Sh[NN + m] = __bfloat16_as_ushort(__float2bfloat16(p - __bfloat162float(hb)));
        }
    }
}

// ---------------- PV: x[n,d] = sum_m P[n,m] V[d,m] -> split planes [b,n,c] ---
__global__ void __launch_bounds__(256)
pv_kernel() {
    __shared__ u16 sPh[128][PS], sPl[128][PS], sVh[64][PS], sVl[64][PS];
    const int bh = blockIdx.y, n0 = blockIdx.x * 128;
    const int t = threadIdx.x, lane = t & 31, w = t >> 5;
    const int wm = w >> 1, wn = w & 1;
    const u16* srow = (const u16*)g_s;
    const u16* Vh = g_vh + (size_t)bh * DH * NN;
    const u16* Vl = g_vl + (size_t)bh * DH * NN;

    const u32 baPh = (u32)__cvta_generic_to_shared(&sPh[0][0]);
    const u32 baPl = (u32)__cvta_generic_to_shared(&sPl[0][0]);
    const u32 baVh = (u32)__cvta_generic_to_shared(&sVh[0][0]);
    const u32 baVl = (u32)__cvta_generic_to_shared(&sVl[0][0]);

    const int pr = t >> 2, psv = (t & 3) * 8;
    uint4 pph[2], ppl[2], pvh, pvl;
    float acc[2][4][4];
#pragma unroll
    for (int i = 0; i < 2; i++)
#pragma unroll
        for (int j = 0; j < 4; j++)
#pragma unroll
            for (int k = 0; k < 4; k++) acc[i][j][k] = 0.f;

    auto load_regs = [&](int m0c) {
        size_t rb0 = (size_t)(bh * NN + n0 + pr) * (2 * NN);
        size_t rb1 = (size_t)(bh * NN + n0 + pr + 64) * (2 * NN);
        pph[0] = *(const uint4*)&srow[rb0 + m0c + psv];
        ppl[0] = *(const uint4*)&srow[rb0 + NN + m0c + psv];
        pph[1] = *(const uint4*)&srow[rb1 + m0c + psv];
        ppl[1] = *(const uint4*)&srow[rb1 + NN + m0c + psv];
        pvh = *(const uint4*)&Vh[(size_t)pr * NN + m0c + psv];
        pvl = *(const uint4*)&Vl[(size_t)pr * NN + m0c + psv];
    };
    auto store_smem = [&]() {
        *(uint4*)&sPh[pr][psv]      = pph[0];
        *(uint4*)&sPl[pr][psv]      = ppl[0];
        *(uint4*)&sPh[pr + 64][psv] = pph[1];
        *(uint4*)&sPl[pr + 64][psv] = ppl[1];
        *(uint4*)&sVh[pr][psv]      = pvh;
        *(uint4*)&sVl[pr][psv]      = pvl;
    };

    load_regs(0); store_smem(); __syncthreads();
    const int NC = NN / 32;
    for (int c = 0; c < NC; c++) {
        if (c + 1 < NC) load_regs((c + 1) * 32);
        mma_step<2, PS>(acc, baPh, baPl, baVh, baVl, lane, wm * 32, wn * 32, 0);
        mma_step<2, PS>(acc, baPh, baPl, baVh, baVl, lane, wm * 32, wn * 32, 16);
        if (c + 1 < NC) { __syncthreads(); store_smem(); __syncthreads(); }
    }

    const int b = bh >> 3, h = bh & 7;
#pragma unroll
    for (int im = 0; im < 2; im++) {
        const int n = n0 + wm * 32 + im * 16 + (lane >> 2);
#pragma unroll
        for (int jn = 0; jn < 4; jn++) {
            float* cc = acc[im][jn];
            const int d  = wn * 32 + jn * 8 + 2 * (lane & 3);
            const int c0i = d * 8 + h, c1i = (d + 1) * 8 + h;
            size_t base0 = ((size_t)b * NN + n) * DD;
            size_t base1 = base0 + (size_t)8 * DD;
            g_xth[base0 + c0i] = b16hi(cc[0]);  g_xtl[base0 + c0i] = b16lo(cc[0]);
            g_xth[base0 + c1i] = b16hi(cc[1]);  g_xtl[base0 + c1i] = b16lo(cc[1]);
            g_xth[base1 + c0i] = b16hi(cc[2]);  g_xtl[base1 + c0i] = b16lo(cc[2]);
            g_xth[base1 + c1i] = b16hi(cc[3]);  g_xtl[base1 + c1i] = b16lo(cc[3]);
        }
    }
}

// ---------------- launch ------------------------------------------------------
extern "C" void kernel_launch(void* const* d_in, const int* in_sizes, int n_in,
                              void* d_out, int out_size) {
    const float* query = (const float*)d_in[0];
    const float* key   = (const float*)d_in[1];
    const float* value = (const float*)d_in[2];
    // d_in[3] = dist (unused)
    const void* mask   = d_in[4];
    const float* Wq = (const float*)d_in[5];
    const float* bq = (const float*)d_in[6];
    const float* Wk = (const float*)d_in[7];
    const float* bk = (const float*)d_in[8];
    const float* Wv = (const float*)d_in[9];
    const float* bv = (const float*)d_in[10];
    const float* Wm = (const float*)d_in[11];
    const float* bm = (const float*)d_in[12];

    float* out  = (float*)d_out;                 // [B, D, N]
    float* out2 = out + (size_t)BB * DD * NN;    // [B, N, N]

    void *pih, *pil, *pwh, *pwl, *pqh, *pql, *pkh, *pkl, *pvh, *pvl, *pxth, *pxtl;
    cudaGetSymbolAddress(&pih, g_ith);
    cudaGetSymbolAddress(&pil, g_itl);
    cudaGetSymbolAddress(&pwh, g_wh);
    cudaGetSymbolAddress(&pwl, g_wl);
    cudaGetSymbolAddress(&pqh, g_qh);
    cudaGetSymbolAddress(&pql, g_ql);
    cudaGetSymbolAddress(&pkh, g_kh);
    cudaGetSymbolAddress(&pkl, g_kl);
    cudaGetSymbolAddress(&pvh, g_vh);
    cudaGetSymbolAddress(&pvl, g_vl);
    cudaGetSymbolAddress(&pxth, g_xth);
    cudaGetSymbolAddress(&pxtl, g_xtl);

    const u16* ith = (const u16*)pih;
    const u16* itl = (const u16*)pil;
    const u16* wh  = (const u16*)pwh;
    const u16* wl  = (const u16*)pwl;
    const size_t IB = (size_t)BB * NN * DD;
    const size_t WB = (size_t)DD * DD;

    cudaFuncSetAttribute(scores_kernel,
                         cudaFuncAttributeMaxDynamicSharedMemorySize, SC_SMEM);

    init_kernel<<<1, 1>>>();
    mask_classify_kernel<<<256, 256>>>((const u32*)mask);
    mask_convert_kernel<<<256, 256>>>(mask);

    presplit_in_kernel<<<dim3(NN / 32, DD / 32, 3 * BB), dim3(32, 8)>>>(query, key, value);
    presplit_w_kernel<<<1024, 256>>>(Wq, Wk, Wv, Wm);

    dim3 gproj(NN / 128, DD / 64, BB);
    proj_kernel<1><<<gproj, 256>>>(ith + 0 * IB, itl + 0 * IB, wh + 0 * WB, wl + 0 * WB, bq, pqh, pql);
    proj_kernel<1><<<gproj, 256>>>(ith + 1 * IB, itl + 1 * IB, wh + 1 * WB, wl + 1 * WB, bk, pkh, pkl);
    proj_kernel<2><<<gproj, 256>>>(ith + 2 * IB, itl + 2 * IB, wh + 2 * WB, wl + 2 * WB, bv, pvh, pvl);

    scores_kernel<<<dim3(NN / 128, NN / 128, BB * HH), 512, SC_SMEM>>>();

    osmax_kernel<<<dim3(NN, BB), 256>>>(out2);

    pv_kernel<<<dim3(NN / 128, BB * HH), 256>>>();

    proj_kernel<0><<<gproj, 256>>>((const u16*)pxth, (const u16*)pxtl,
                                   wh + 3 * WB, wl + 3 * WB, bm, out, nullptr);
}